// round 12
// baseline (speedup 1.0000x reference)
#include <cuda_runtime.h>
#include <cuda_fp16.h>
#include <math.h>
#include <stdint.h>

#define NXI 512
#define LDIM 128
#define NSTATES 128
#define NIN 64
#define HDIM 1152           // 2*NXI + LDIM
#define BATCHN 32768
#define EPSV 0.001f
#define ALPHA 0.55f
#define NEWTON_ITERS 7      // + fused first step = 8 squarings

// ---------------- device scratch ----------------
__device__ float g_H[HDIM * HDIM];
__device__ float g_Zf[2][NXI * NXI];
__device__ float g_D11[LDIM * LDIM];
__device__ float g_LamInv[LDIM];
__device__ float g_pre[(size_t)BATCHN * LDIM];
__device__ unsigned g_barcnt, g_barep;     // software grid barrier state (zero-init)

// split-fp16 operand arrays
__device__ __half g_AH[(size_t)BATCHN * 768];   // [xi | eps | w]
__device__ __half g_AL[(size_t)BATCHN * 768];
__device__ __half g_WpreH[LDIM * 768];
__device__ __half g_WpreL[LDIM * 768];
__device__ __half g_WoutH[640 * 768];           // rows 576..639 stay zero
__device__ __half g_WoutL[640 * 768];
__device__ __half g_XtH[HDIM * HDIM];
__device__ __half g_XtL[HDIM * HDIM];
__device__ __half g_MH[NXI * NXI], g_ML[NXI * NXI];
__device__ __half g_ZH[2][NXI * NXI], g_ZL[2][NXI * NXI];
__device__ __half g_ZTH[2][NXI * NXI], g_ZTL[2][NXI * NXI];
__device__ __half g_TtH[NXI * NXI], g_TtL[NXI * NXI];
__device__ __half g_RtH[768 * NXI], g_RtL[768 * NXI];

// ---------------- PTX helpers ----------------
__device__ __forceinline__ uint32_t smem_u32(const void* p) {
    uint32_t a;
    asm("{ .reg .u64 t; cvta.to.shared.u64 t, %1; cvt.u32.u64 %0, t; }" : "=r"(a) : "l"(p));
    return a;
}
#define LDSM4(r0, r1, r2, r3, addr) \
    asm volatile("ldmatrix.sync.aligned.m8n8.x4.shared.b16 {%0,%1,%2,%3}, [%4];" \
                 : "=r"(r0), "=r"(r1), "=r"(r2), "=r"(r3) : "r"(addr))
#define MMA16816(d, a, b0, b1) \
    asm volatile("mma.sync.aligned.m16n8k16.row.col.f32.f16.f16.f32 " \
                 "{%0,%1,%2,%3},{%4,%5,%6,%7},{%8,%9},{%0,%1,%2,%3};" \
                 : "+f"(d[0]), "+f"(d[1]), "+f"(d[2]), "+f"(d[3]) \
                 : "r"(a[0]), "r"(a[1]), "r"(a[2]), "r"(a[3]), "r"(b0), "r"(b1))
#define CPA16(smaddr, gptr) \
    asm volatile("cp.async.cg.shared.global [%0], [%1], 16;" :: "r"(smaddr), "l"(gptr))
#define CPCOMMIT() asm volatile("cp.async.commit_group;" ::: "memory")
#define CPWAIT1()  asm volatile("cp.async.wait_group 1;" ::: "memory")
#define CPWAIT0()  asm volatile("cp.async.wait_group 0;" ::: "memory")

__device__ __forceinline__ void split_store(__half* H, __half* L, size_t idx, float v) {
    __half h = __float2half(v);
    H[idx] = h;
    L[idx] = __float2half(v - __half2float(h));
}

// software grid barrier (all NBLK CTAs co-resident). Replay-safe.
__device__ __forceinline__ void gridbar(int nblk) {
    __threadfence();
    __syncthreads();
    if (threadIdx.x == 0) {
        unsigned e = ((volatile unsigned*)&g_barep)[0];
        unsigned t = atomicAdd(&g_barcnt, 1);
        if (t == (unsigned)nblk - 1) {
            g_barcnt = 0;
            __threadfence();
            atomicAdd(&g_barep, 1);
        } else {
            while (((volatile unsigned*)&g_barep)[0] == e) {}
        }
    }
    __syncthreads();
    __threadfence();
}

// ============ big batch GEMM (128x128 tiles, cp.async 3-stage, 1 sync/chunk) ============
// 2-product fp16 split: hh + h_a*l_b. buffer(chunk) = chunk % 3 for read AND prefetch.
#define BK 32
#define LDSW (BK + 8)
#define SA_AH 0u
#define SA_BH 10240u
#define SA_BL 20480u
#define SBUF  30720u
__global__ __launch_bounds__(256) void mma_gemm(
    const __half* __restrict__ Ah,
    const __half* __restrict__ Bh, const __half* __restrict__ Bl,
    int nchunks, int skip_at, int skip_amt, int lda, int ldb,
    float* __restrict__ out0, float* __restrict__ out1, int mode) {
    extern __shared__ char dsm[];
    const uint32_t smb = smem_u32(dsm);
    const int tid = threadIdx.x;
    const int wid = tid >> 5, lane = tid & 31;
    const size_t m0 = (size_t)blockIdx.y * 128;
    const int n0 = blockIdx.x * 128;
    const int wm = (wid & 3) * 32;
    const int wn = (wid >> 2) * 64;

    float acc[2][8][4] = {};
    const int lr = tid >> 1;
    const int lc = (tid & 1) * 16;
    const int am = wm + (lane & 15);
    const int ak = (lane >> 4) * 8;
    const int bn = wn + (lane & 7) + (lane >> 4) * 8;
    const int bk = ((lane >> 3) & 1) * 8;

    auto issue = [&](int c) {
        const int kc = c * BK;
        const int col = (kc >= skip_at) ? kc + skip_amt : kc;
        const size_t oa = (m0 + lr) * (size_t)lda + col + lc;
        const size_t ob = (size_t)(n0 + lr) * ldb + col + lc;
        const uint32_t so = smb + (uint32_t)(c % 3) * SBUF + (uint32_t)(lr * LDSW + lc) * 2;
        CPA16(so + SA_AH, Ah + oa); CPA16(so + SA_AH + 16, Ah + oa + 8);
        CPA16(so + SA_BH, Bh + ob); CPA16(so + SA_BH + 16, Bh + ob + 8);
        CPA16(so + SA_BL, Bl + ob); CPA16(so + SA_BL + 16, Bl + ob + 8);
        CPCOMMIT();
    };

    issue(0);
    if (nchunks > 1) issue(1);
    for (int c = 0; c < nchunks; ++c) {
        if (c + 1 < nchunks) { CPWAIT1(); } else { CPWAIT0(); }
        __syncthreads();
        if (c + 2 < nchunks) issue(c + 2);
        const uint32_t bb = smb + (uint32_t)(c % 3) * SBUF;
#pragma unroll
        for (int k16 = 0; k16 < BK; k16 += 16) {
            uint32_t ahf[2][4], bhf[4][4], blf[4][4];
#pragma unroll
            for (int mi = 0; mi < 2; ++mi) {
                const uint32_t off = bb + (uint32_t)(((am + mi * 16) * LDSW + ak + k16) * 2);
                LDSM4(ahf[mi][0], ahf[mi][1], ahf[mi][2], ahf[mi][3], off + SA_AH);
            }
#pragma unroll
            for (int j = 0; j < 4; ++j) {
                const uint32_t off = bb + (uint32_t)(((bn + j * 16) * LDSW + bk + k16) * 2);
                LDSM4(bhf[j][0], bhf[j][1], bhf[j][2], bhf[j][3], off + SA_BH);
                LDSM4(blf[j][0], blf[j][1], blf[j][2], blf[j][3], off + SA_BL);
            }
#pragma unroll
            for (int mi = 0; mi < 2; ++mi)
#pragma unroll
                for (int j = 0; j < 4; ++j)
#pragma unroll
                    for (int h = 0; h < 2; ++h) {
                        float* d = acc[mi][j * 2 + h];
                        MMA16816(d, ahf[mi], bhf[j][h * 2], bhf[j][h * 2 + 1]);
                        MMA16816(d, ahf[mi], blf[j][h * 2], blf[j][h * 2 + 1]);
                    }
        }
    }
    const int rrow = lane >> 2;
    const int rcol = (lane & 3) * 2;
#pragma unroll
    for (int mi = 0; mi < 2; ++mi)
#pragma unroll
        for (int j = 0; j < 8; ++j) {
            const float* d = acc[mi][j];
            const int n = n0 + wn + j * 8 + rcol;
#pragma unroll
            for (int half = 0; half < 2; ++half) {
                const size_t m = m0 + wm + mi * 16 + rrow + half * 8;
                const float v0 = d[half * 2 + 0], v1 = d[half * 2 + 1];
                if (mode == 0) {
                    *(float2*)(out0 + m * 128 + n) = make_float2(v0, v1);
                } else {
                    if (n < NIN) *(float2*)(out0 + m * NIN + n) = make_float2(v0, v1);
                    else if (n < 576) *(float2*)(out1 + m * NXI + (n - NIN)) = make_float2(v0, v1);
                }
            }
        }
}

// ============ 64x64 GEMM core (fp16 3-product), logical tid + K offset ============
#define LDS2 (BK + 8)
__device__ __forceinline__ void gemm64_core(
    const __half* __restrict__ Ah, const __half* __restrict__ Al,
    const __half* __restrict__ Bh, const __half* __restrict__ Bl,
    int nchunks, int koff, int lda, int ldb, int m0, int n0,
    __half* sAh, __half* sAl, __half* sBh, __half* sBl,
    float acc[2][4][4], int t) {
    const int wid = t >> 5, lane = t & 31;
    const int wm = (wid & 1) * 32;
    const int wn = (wid >> 1) * 32;
    const int lr = t >> 1;
    const int lc = (t & 1) * 16;
    const uint32_t uAh = smem_u32(sAh), uAl = smem_u32(sAl);
    const uint32_t uBh = smem_u32(sBh), uBl = smem_u32(sBl);
    const int am = wm + (lane & 15);
    const int ak = (lane >> 4) * 8;
    const int bn = wn + (lane & 7) + (lane >> 4) * 8;
    const int bk = ((lane >> 3) & 1) * 8;

#pragma unroll
    for (int mi = 0; mi < 2; ++mi)
#pragma unroll
        for (int j = 0; j < 4; ++j)
#pragma unroll
            for (int q = 0; q < 4; ++q) acc[mi][j][q] = 0.0f;

    uint4 pa[2][2], pb[2][2];
    auto gload = [&](int c) {
        const int col = koff + c * BK;
        const size_t oa = (size_t)(m0 + lr) * lda + col + lc;
        const size_t ob = (size_t)(n0 + lr) * ldb + col + lc;
        pa[0][0] = *(const uint4*)(Ah + oa); pa[0][1] = *(const uint4*)(Ah + oa + 8);
        pa[1][0] = *(const uint4*)(Al + oa); pa[1][1] = *(const uint4*)(Al + oa + 8);
        pb[0][0] = *(const uint4*)(Bh + ob); pb[0][1] = *(const uint4*)(Bh + ob + 8);
        pb[1][0] = *(const uint4*)(Bl + ob); pb[1][1] = *(const uint4*)(Bl + ob + 8);
    };

    gload(0);
    for (int c = 0; c < nchunks; ++c) {
        const int so = lr * LDS2 + lc;
        *(uint4*)(sAh + so) = pa[0][0]; *(uint4*)(sAh + so + 8) = pa[0][1];
        *(uint4*)(sAl + so) = pa[1][0]; *(uint4*)(sAl + so + 8) = pa[1][1];
        *(uint4*)(sBh + so) = pb[0][0]; *(uint4*)(sBh + so + 8) = pb[0][1];
        *(uint4*)(sBl + so) = pb[1][0]; *(uint4*)(sBl + so + 8) = pb[1][1];
        __syncthreads();
        if (c + 1 < nchunks) gload(c + 1);
#pragma unroll
        for (int k16 = 0; k16 < BK; k16 += 16) {
            uint32_t ahf[2][4], alf[2][4], bhf[2][4], blf[2][4];
#pragma unroll
            for (int mi = 0; mi < 2; ++mi) {
                const uint32_t off = (uint32_t)(((am + mi * 16) * LDS2 + ak + k16) * 2);
                LDSM4(ahf[mi][0], ahf[mi][1], ahf[mi][2], ahf[mi][3], uAh + off);
                LDSM4(alf[mi][0], alf[mi][1], alf[mi][2], alf[mi][3], uAl + off);
            }
#pragma unroll
            for (int j = 0; j < 2; ++j) {
                const uint32_t off = (uint32_t)(((bn + j * 16) * LDS2 + bk + k16) * 2);
                LDSM4(bhf[j][0], bhf[j][1], bhf[j][2], bhf[j][3], uBh + off);
                LDSM4(blf[j][0], blf[j][1], blf[j][2], blf[j][3], uBl + off);
            }
#pragma unroll
            for (int mi = 0; mi < 2; ++mi)
#pragma unroll
                for (int j = 0; j < 2; ++j)
#pragma unroll
                    for (int h = 0; h < 2; ++h) {
                        float* d = acc[mi][j * 2 + h];
                        MMA16816(d, ahf[mi], bhf[j][h * 2], bhf[j][h * 2 + 1]);
                        MMA16816(d, ahf[mi], blf[j][h * 2], blf[j][h * 2 + 1]);
                        MMA16816(d, alf[mi], bhf[j][h * 2], bhf[j][h * 2 + 1]);
                    }
        }
        __syncthreads();
    }
}

// standalone small GEMM (used only for full H now). emode 0 = fp32 out (+eps diag)
__global__ __launch_bounds__(128) void tc2(
    const __half* __restrict__ Ah, const __half* __restrict__ Al,
    const __half* __restrict__ Bh, const __half* __restrict__ Bl,
    int K, int lda, int ldb,
    float* __restrict__ outf, int ldc, int emode) {
    __shared__ __half sAh[64 * LDS2], sAl[64 * LDS2];
    __shared__ __half sBh[64 * LDS2], sBl[64 * LDS2];
    const int tid = threadIdx.x;
    const int wid = tid >> 5, lane = tid & 31;
    const int m0 = blockIdx.y * 64;
    const int n0 = blockIdx.x * 64;
    const int wm = (wid & 1) * 32;
    const int wn = (wid >> 1) * 32;
    float acc[2][4][4];
    gemm64_core(Ah, Al, Bh, Bl, K / BK, 0, lda, ldb, m0, n0, sAh, sAl, sBh, sBl, acc, tid);

    const int rrow = lane >> 2;
    const int rcol = (lane & 3) * 2;
#pragma unroll
    for (int mi = 0; mi < 2; ++mi)
#pragma unroll
        for (int j = 0; j < 4; ++j) {
            const float* d = acc[mi][j];
            const int n = n0 + wn + j * 8 + rcol;
#pragma unroll
            for (int half = 0; half < 2; ++half) {
                const int m = m0 + wm + mi * 16 + rrow + half * 8;
                float v0 = d[half * 2 + 0], v1 = d[half * 2 + 1];
                if (emode == 0) {
                    if (m == n) v0 += EPSV;
                    if (m == n + 1) v1 += EPSV;
                }
                *(float2*)(outf + (size_t)m * ldc + n) = make_float2(v0, v1);
            }
        }
}

// ============ fused persistent Newton (k-split 256-thread CTAs) + Wout solve tail ============
#define NWT_BLOCKS 64
__global__ __launch_bounds__(256) void newton_fused() {
    __shared__ __half smt[8][64 * LDS2];       // 40 KB: 4 tile buffers per warpgroup
    const int tid = threadIdx.x;
    const int wg = tid >> 7;                   // warpgroup 0/1 = K halves
    const int wt = tid & 127;
    __half* bAh = smt[wg * 4 + 0];
    __half* bAl = smt[wg * 4 + 1];
    __half* bBh = smt[wg * 4 + 2];
    __half* bBl = smt[wg * 4 + 3];
    float* red = (float*)smt;                  // 16 KB scratch, reused after tiles drain
    const int m0 = (blockIdx.x >> 3) * 64;
    const int n0 = (blockIdx.x & 7) * 64;
    const int wid = wt >> 5, lane = wt & 31;
    const int wm = (wid & 1) * 32;
    const int wn = (wid >> 1) * 32;
    const int rrow = lane >> 2;
    const int rcol = (lane & 3) * 2;
    float acc[2][4][4];

    auto half_gemm = [&](const __half* Ah, const __half* Al,
                         const __half* Bh, const __half* Bl, int tm0, int tn0) {
        gemm64_core(Ah, Al, Bh, Bl, (NXI / BK) / 2, wg * (NXI / 2), NXI, NXI,
                    tm0, tn0, bAh, bAl, bBh, bBl, acc, wt);
        if (wg == 1) {
            float* dst = red + wt * 32;
#pragma unroll
            for (int mi = 0; mi < 2; ++mi)
#pragma unroll
                for (int j = 0; j < 4; ++j)
#pragma unroll
                    for (int q = 0; q < 4; ++q)
                        dst[(mi * 4 + j) * 4 + q] = acc[mi][j][q];
        }
        __syncthreads();
        if (wg == 0) {
            const float* src = red + wt * 32;
#pragma unroll
            for (int mi = 0; mi < 2; ++mi)
#pragma unroll
                for (int j = 0; j < 4; ++j)
#pragma unroll
                    for (int q = 0; q < 4; ++q)
                        acc[mi][j][q] += src[(mi * 4 + j) * 4 + q];
        }
        __syncthreads();
    };

    int cur = 0;
    for (int it = 0; it < NEWTON_ITERS; ++it) {
        // phase 1: T = M * Z^T -> transposed splits Tt
        half_gemm(g_MH, g_ML, g_ZTH[cur], g_ZTL[cur], m0, n0);
        if (wg == 0) {
#pragma unroll
            for (int mi = 0; mi < 2; ++mi)
#pragma unroll
                for (int j = 0; j < 4; ++j) {
                    const float* d = acc[mi][j];
                    const int n = n0 + wn + j * 8 + rcol;
#pragma unroll
                    for (int half = 0; half < 2; ++half) {
                        const int m = m0 + wm + mi * 16 + rrow + half * 8;
                        split_store(g_TtH, g_TtL, (size_t)n * NXI + m, d[half * 2 + 0]);
                        split_store(g_TtH, g_TtL, (size_t)(n + 1) * NXI + m, d[half * 2 + 1]);
                    }
                }
        }
        gridbar(NWT_BLOCKS);

        // phase 2: Zn = 2*Z - Z*T
        half_gemm(g_ZH[cur], g_ZL[cur], g_TtH, g_TtL, m0, n0);
        if (wg == 0) {
            const float* zin = g_Zf[cur];
            float* zout = g_Zf[cur ^ 1];
            const int nx = cur ^ 1;
#pragma unroll
            for (int mi = 0; mi < 2; ++mi)
#pragma unroll
                for (int j = 0; j < 4; ++j) {
                    const float* d = acc[mi][j];
                    const int n = n0 + wn + j * 8 + rcol;
#pragma unroll
                    for (int half = 0; half < 2; ++half) {
                        const int m = m0 + wm + mi * 16 + rrow + half * 8;
                        const size_t o = (size_t)m * NXI + n;
                        float v0 = 2.0f * zin[o] - d[half * 2 + 0];
                        float v1 = 2.0f * zin[o + 1] - d[half * 2 + 1];
                        *(float2*)(zout + o) = make_float2(v0, v1);
                        split_store(g_ZH[nx], g_ZL[nx], o, v0);
                        split_store(g_ZH[nx], g_ZL[nx], o + 1, v1);
                        split_store(g_ZTH[nx], g_ZTL[nx], (size_t)n * NXI + m, v0);
                        split_store(g_ZTH[nx], g_ZTL[nx], (size_t)(n + 1) * NXI + m, v1);
                    }
                }
        }
        gridbar(NWT_BLOCKS);
        cur ^= 1;
    }

    // solve tail: Wout[64+m, n] = sum_k Z[m,k] * Rt[n,k]  (96 tiles over 64 CTAs)
    const int fin = NEWTON_ITERS & 1;
    for (int t = blockIdx.x; t < 96; t += NWT_BLOCKS) {
        const int sm0 = (t & 7) * 64;
        const int sn0 = (t >> 3) * 64;
        half_gemm(g_ZH[fin], g_ZL[fin], g_RtH, g_RtL, sm0, sn0);
        if (wg == 0) {
#pragma unroll
            for (int mi = 0; mi < 2; ++mi)
#pragma unroll
                for (int j = 0; j < 4; ++j) {
                    const float* d = acc[mi][j];
                    const int n = sn0 + wn + j * 8 + rcol;
#pragma unroll
                    for (int half = 0; half < 2; ++half) {
                        const int m = sm0 + wm + mi * 16 + rrow + half * 8;
                        const size_t o = (size_t)(64 + m) * 768 + n;
                        split_store(g_WoutH, g_WoutL, o, d[half * 2 + 0]);
                        split_store(g_WoutH, g_WoutL, o + 1, d[half * 2 + 1]);
                    }
                }
        }
    }
}

// ---------------- builders ----------------
__global__ void conv_Xt(const float* __restrict__ X) {
    __shared__ float t[32][33];
    const int bx = blockIdx.x * 32, by = blockIdx.y * 32;
    const int tx = threadIdx.x, ty = threadIdx.y;
#pragma unroll
    for (int r = 0; r < 32; r += 8)
        t[ty + r][tx] = X[(size_t)(by + ty + r) * HDIM + bx + tx];
    __syncthreads();
#pragma unroll
    for (int r = 0; r < 32; r += 8) {
        const float v = t[tx][ty + r];
        split_store(g_XtH, g_XtL, (size_t)(bx + ty + r) * HDIM + by + tx, v);
    }
}
// Wpre cols 0..511 = -H21[r][c] = -sum_k X[k][512+r] * X[k][c]   (direct from X)
__global__ __launch_bounds__(256) void build_Wpre_simt(const float* __restrict__ X) {
    int idx = blockIdx.x * 256 + threadIdx.x;       // 65536
    int r = idx >> 9, c = idx & 511;
    const float* xa = X + 512 + r;
    const float* xb = X + c;
    float a0 = 0.f, a1 = 0.f, a2 = 0.f, a3 = 0.f;
    for (int k = 0; k < HDIM; k += 4) {
        a0 = fmaf(xa[(size_t)k * HDIM], xb[(size_t)k * HDIM], a0);
        a1 = fmaf(xa[(size_t)(k + 1) * HDIM], xb[(size_t)(k + 1) * HDIM], a1);
        a2 = fmaf(xa[(size_t)(k + 2) * HDIM], xb[(size_t)(k + 2) * HDIM], a2);
        a3 = fmaf(xa[(size_t)(k + 3) * HDIM], xb[(size_t)(k + 3) * HDIM], a3);
    }
    split_store(g_WpreH, g_WpreL, (size_t)r * 768 + c, -((a0 + a1) + (a2 + a3)));
}
// D11 + LamInv from H22[i][j] = sum_k X[k][512+i] * X[k][512+j]   (direct from X)
__global__ __launch_bounds__(256) void build_D11_simt(const float* __restrict__ X) {
    int idx = blockIdx.x * 256 + threadIdx.x;       // 16384
    int i = idx >> 7, j = idx & 127;
    const float* xa = X + 512 + i;
    const float* xb = X + 512 + j;
    float a0 = 0.f, a1 = 0.f, a2 = 0.f, a3 = 0.f;
    for (int k = 0; k < HDIM; k += 4) {
        a0 = fmaf(xa[(size_t)k * HDIM], xb[(size_t)k * HDIM], a0);
        a1 = fmaf(xa[(size_t)(k + 1) * HDIM], xb[(size_t)(k + 1) * HDIM], a1);
        a2 = fmaf(xa[(size_t)(k + 2) * HDIM], xb[(size_t)(k + 2) * HDIM], a2);
        a3 = fmaf(xa[(size_t)(k + 3) * HDIM], xb[(size_t)(k + 3) * HDIM], a3);
    }
    float h = (a0 + a1) + (a2 + a3);
    g_D11[idx] = (j < i) ? -h : 0.0f;
    if (j == i) g_LamInv[i] = 2.0f / (h + EPSV);
}
// M = D^-1 E (splits); Z1 = 2a*I - a^2*M ; dinv inline
__global__ void build_MZ(const float* __restrict__ Y) {
    int idx = blockIdx.x * blockDim.x + threadIdx.x;
    if (idx >= NXI * NXI) return;
    int i = idx >> 9, j = idx & 511;
    float dinv = 2.0f / (g_H[(size_t)i * HDIM + i] + g_H[(size_t)(640 + i) * HDIM + 640 + i]);
    float e = 0.5f * (g_H[(size_t)i * HDIM + j] + g_H[(size_t)(640 + i) * HDIM + 640 + j] +
                      Y[(size_t)i * NXI + j] - Y[(size_t)j * NXI + i]);
    float m = dinv * e;
    split_store(g_MH, g_ML, idx, m);
    float z = ((i == j) ? 2.0f * ALPHA : 0.0f) - ALPHA * ALPHA * m;
    g_Zf[0][idx] = z;
    split_store(g_ZH[0], g_ZL[0], idx, z);
    split_store(g_ZTH[0], g_ZTL[0], (size_t)j * NXI + i, z);
}
__global__ void build_Rt(const float* __restrict__ B2) {
    int idx = blockIdx.x * blockDim.x + threadIdx.x;
    if (idx >= NXI * 768) return;
    int i = idx / 768, c = idx - i * 768;
    float dinv = 2.0f / (g_H[(size_t)i * HDIM + i] + g_H[(size_t)(640 + i) * HDIM + 640 + i]);
    float v = (c < 640) ? g_H[(size_t)(640 + i) * HDIM + c] : B2[i * NSTATES + (c - 640)];
    split_store(g_RtH, g_RtL, (size_t)c * NXI + i, dinv * v);
}
__global__ void build_WoutTop(const float* __restrict__ C2, const float* __restrict__ D21,
                              const float* __restrict__ D22) {
    int idx = blockIdx.x * blockDim.x + threadIdx.x;
    if (idx >= NIN * 768) return;
    int rr = idx / 768, c = idx - rr * 768;
    float v = (c < NXI) ? C2[rr * NXI + c]
                        : (c < 640 ? D21[rr * LDIM + (c - NXI)] : D22[rr * NSTATES + (c - 640)]);
    split_store(g_WoutH, g_WoutL, idx, v);
}
__global__ void build_WpreD12(const float* __restrict__ D12) {
    int idx = blockIdx.x * blockDim.x + threadIdx.x;
    if (idx >= LDIM * NSTATES) return;
    int rr = idx >> 7, c = idx & 127;
    split_store(g_WpreH, g_WpreL, (size_t)rr * 768 + 640 + c, D12[rr * NSTATES + c]);
}
__global__ void conv_A(const float* __restrict__ xi, const float* __restrict__ w) {
    size_t idx = (size_t)blockIdx.x * blockDim.x + threadIdx.x;
    size_t b = idx / 160;
    int c0 = (int)(idx - b * 160) * 4;
    if (b >= BATCHN) return;
    float4 v;
    int dc;
    if (c0 < NXI) { v = *(const float4*)(xi + b * NXI + c0); dc = c0; }
    else          { v = *(const float4*)(w + b * NSTATES + (c0 - NXI)); dc = c0 + 128; }
    size_t o = b * 768 + dc;
    split_store(g_AH, g_AL, o + 0, v.x);
    split_store(g_AH, g_AL, o + 1, v.y);
    split_store(g_AH, g_AL, o + 2, v.z);
    split_store(g_AH, g_AL, o + 3, v.w);
}

// ---------------- tanh forward-substitution scan ----------------
__global__ __launch_bounds__(64) void eps_kernel() {
    __shared__ float es[128 * 64];
    __shared__ float li[128];
    int tid = threadIdx.x;
    size_t b = (size_t)blockIdx.x * 64 + tid;
    for (int i = tid; i < 128; i += 64) li[i] = g_LamInv[i];
    __syncthreads();
    for (int i = 0; i < 128; ++i) {
        float v = g_pre[b * 128 + i];
        const float* __restrict__ dr = &g_D11[i * 128];
        float v0 = 0.f, v1 = 0.f, v2 = 0.f, v3 = 0.f;
        int j = 0;
        for (; j + 3 < i; j += 4) {
            v0 = fmaf(es[(j + 0) * 64 + tid], dr[j + 0], v0);
            v1 = fmaf(es[(j + 1) * 64 + tid], dr[j + 1], v1);
            v2 = fmaf(es[(j + 2) * 64 + tid], dr[j + 2], v2);
            v3 = fmaf(es[(j + 3) * 64 + tid], dr[j + 3], v3);
        }
        for (; j < i; ++j) v0 = fmaf(es[j * 64 + tid], dr[j], v0);
        v += (v0 + v1) + (v2 + v3);
        es[i * 64 + tid] = tanhf(v * li[i]);
    }
    for (int i = 0; i < 128; ++i)
        split_store(g_AH, g_AL, b * 768 + 512 + i, es[i * 64 + tid]);
}

// ---------------- launch ----------------
extern "C" void kernel_launch(void* const* d_in, const int* in_sizes, int n_in,
                              void* d_out, int out_size) {
    (void)in_sizes; (void)n_in; (void)out_size;
    const float* w   = (const float*)d_in[1];
    const float* xi  = (const float*)d_in[2];
    const float* X   = (const float*)d_in[3];
    const float* Y   = (const float*)d_in[4];
    const float* B2  = (const float*)d_in[5];
    const float* C2  = (const float*)d_in[6];
    const float* D21 = (const float*)d_in[7];
    const float* D22 = (const float*)d_in[8];
    const float* D12 = (const float*)d_in[9];
    float* out   = (float*)d_out;
    float* out_u = out;
    float* out_x = out + (size_t)BATCHN * NIN;

    static cudaStream_t s2;
    static cudaEvent_t evStart, evJoin;
    static bool inited = false;
    if (!inited) {
        cudaStreamCreateWithFlags(&s2, cudaStreamNonBlocking);
        cudaEventCreateWithFlags(&evStart, cudaEventDisableTiming);
        cudaEventCreateWithFlags(&evJoin, cudaEventDisableTiming);
        cudaFuncSetAttribute(mma_gemm, cudaFuncAttributeMaxDynamicSharedMemorySize, 3 * SBUF);
        inited = true;
    }

    float *pH, *pPre;
    __half *pAH, *pWpreH, *pWpreL, *pWoutH, *pWoutL, *pXtH, *pXtL;
    cudaGetSymbolAddress((void**)&pH, g_H);
    cudaGetSymbolAddress((void**)&pPre, g_pre);
    cudaGetSymbolAddress((void**)&pAH, g_AH);
    cudaGetSymbolAddress((void**)&pWpreH, g_WpreH);
    cudaGetSymbolAddress((void**)&pWpreL, g_WpreL);
    cudaGetSymbolAddress((void**)&pWoutH, g_WoutH);
    cudaGetSymbolAddress((void**)&pWoutL, g_WoutL);
    cudaGetSymbolAddress((void**)&pXtH, g_XtH);
    cudaGetSymbolAddress((void**)&pXtL, g_XtL);

    // ---- fork: branch A (s2) is fully independent of branch B ----
    cudaEventRecord(evStart, 0);
    cudaStreamWaitEvent(s2, evStart, 0);

    // branch A (s2): conv_A, Wpre/D11 direct from X, pre-GEMM, eps scan
    conv_A<<<(BATCHN * 160 + 255) / 256, 256, 0, s2>>>(xi, w);
    build_WpreD12<<<(LDIM * NSTATES + 255) / 256, 256, 0, s2>>>(D12);
    build_Wpre_simt<<<256, 256, 0, s2>>>(X);
    build_D11_simt<<<64, 256, 0, s2>>>(X);
    mma_gemm<<<dim3(1, BATCHN / 128), 256, 3 * SBUF, s2>>>(
        pAH, pWpreH, pWpreL, 20, 512, 128, 768, 768, pPre, nullptr, 0);
    eps_kernel<<<BATCHN / 64, 64, 0, s2>>>();
    cudaEventRecord(evJoin, s2);

    // branch B (s0): Xt -> full H -> MZ/Rt/WoutTop -> fused Newton + solve
    conv_Xt<<<dim3(HDIM / 32, HDIM / 32), dim3(32, 8)>>>(X);
    tc2<<<dim3(HDIM / 64, HDIM / 64), 128>>>(
        pXtH, pXtL, pXtH, pXtL, HDIM, HDIM, HDIM, pH, HDIM, 0);
    build_MZ<<<(NXI * NXI + 255) / 256, 256>>>(Y);
    build_Rt<<<(NXI * 768 + 255) / 256, 256>>>(B2);
    build_WoutTop<<<(NIN * 768 + 255) / 256, 256>>>(C2, D21, D22);
    newton_fused<<<NWT_BLOCKS, 256>>>();

    // ---- join ----
    cudaStreamWaitEvent(0, evJoin, 0);

    // [u | xi_] = [xi|eps|w] @ Wout^T  (2-product fp16 split)
    mma_gemm<<<dim3(5, BATCHN / 128), 256, 3 * SBUF>>>(
        pAH, pWoutH, pWoutL, 24, 1 << 30, 0, 768, 768, out_u, out_x, 1);
}

// round 13
// speedup vs baseline: 1.0620x; 1.0620x over previous
#include <cuda_runtime.h>
#include <cuda_fp16.h>
#include <math.h>
#include <stdint.h>

#define NXI 512
#define LDIM 128
#define NSTATES 128
#define NIN 64
#define HDIM 1152           // 2*NXI + LDIM
#define BATCHN 32768
#define EPSV 0.001f
#define ALPHA 0.55f
#define NEWTON_ITERS 7      // + fused first step = 8 squarings

// ---------------- device scratch ----------------
__device__ float g_H[HDIM * HDIM];
__device__ float g_Zf[2][NXI * NXI];
__device__ float g_D11[LDIM * LDIM];
__device__ float g_LamInv[LDIM];
__device__ float g_pre[(size_t)BATCHN * LDIM];
__device__ unsigned g_barcnt, g_barep;     // software grid barrier state (zero-init)

// split-fp16 operand arrays
__device__ __half g_AH[(size_t)BATCHN * 768];   // [xi | eps | w]
__device__ __half g_AL[(size_t)BATCHN * 768];
__device__ __half g_WpreH[LDIM * 768];
__device__ __half g_WpreL[LDIM * 768];
__device__ __half g_WoutH[640 * 768];           // rows 576..639 stay zero
__device__ __half g_WoutL[640 * 768];
__device__ __half g_XtH[HDIM * HDIM];
__device__ __half g_XtL[HDIM * HDIM];
__device__ __half g_MH[NXI * NXI], g_ML[NXI * NXI];
__device__ __half g_ZH[2][NXI * NXI], g_ZL[2][NXI * NXI];
__device__ __half g_ZTH[2][NXI * NXI], g_ZTL[2][NXI * NXI];
__device__ __half g_TtH[NXI * NXI], g_TtL[NXI * NXI];
__device__ __half g_RtH[768 * NXI], g_RtL[768 * NXI];

// ---------------- PTX helpers ----------------
__device__ __forceinline__ uint32_t smem_u32(const void* p) {
    uint32_t a;
    asm("{ .reg .u64 t; cvta.to.shared.u64 t, %1; cvt.u32.u64 %0, t; }" : "=r"(a) : "l"(p));
    return a;
}
#define LDSM4(r0, r1, r2, r3, addr) \
    asm volatile("ldmatrix.sync.aligned.m8n8.x4.shared.b16 {%0,%1,%2,%3}, [%4];" \
                 : "=r"(r0), "=r"(r1), "=r"(r2), "=r"(r3) : "r"(addr))
#define MMA16816(d, a, b0, b1) \
    asm volatile("mma.sync.aligned.m16n8k16.row.col.f32.f16.f16.f32 " \
                 "{%0,%1,%2,%3},{%4,%5,%6,%7},{%8,%9},{%0,%1,%2,%3};" \
                 : "+f"(d[0]), "+f"(d[1]), "+f"(d[2]), "+f"(d[3]) \
                 : "r"(a[0]), "r"(a[1]), "r"(a[2]), "r"(a[3]), "r"(b0), "r"(b1))
#define CPA16(smaddr, gptr) \
    asm volatile("cp.async.cg.shared.global [%0], [%1], 16;" :: "r"(smaddr), "l"(gptr))
#define CPCOMMIT() asm volatile("cp.async.commit_group;" ::: "memory")
#define CPWAIT1()  asm volatile("cp.async.wait_group 1;" ::: "memory")
#define CPWAIT0()  asm volatile("cp.async.wait_group 0;" ::: "memory")

__device__ __forceinline__ void split_store(__half* H, __half* L, size_t idx, float v) {
    __half h = __float2half(v);
    H[idx] = h;
    L[idx] = __float2half(v - __half2float(h));
}

// software grid barrier (all NBLK CTAs co-resident). Replay-safe.
__device__ __forceinline__ void gridbar(int nblk) {
    __threadfence();
    __syncthreads();
    if (threadIdx.x == 0) {
        unsigned e = ((volatile unsigned*)&g_barep)[0];
        unsigned t = atomicAdd(&g_barcnt, 1);
        if (t == (unsigned)nblk - 1) {
            g_barcnt = 0;
            __threadfence();
            atomicAdd(&g_barep, 1);
        } else {
            while (((volatile unsigned*)&g_barep)[0] == e) {}
        }
    }
    __syncthreads();
    __threadfence();
}

// ============ big batch GEMM (128x128 tiles, cp.async 3-stage, 1 sync/chunk) ============
// 2-product fp16 split: hh + h_a*l_b. buffer(chunk) = chunk % 3 for read AND prefetch.
#define BK 32
#define LDSW (BK + 8)
#define SA_AH 0u
#define SA_BH 10240u
#define SA_BL 20480u
#define SBUF  30720u
__global__ __launch_bounds__(256) void mma_gemm(
    const __half* __restrict__ Ah,
    const __half* __restrict__ Bh, const __half* __restrict__ Bl,
    int nchunks, int skip_at, int skip_amt, int lda, int ldb,
    float* __restrict__ out0, float* __restrict__ out1, int mode) {
    extern __shared__ char dsm[];
    const uint32_t smb = smem_u32(dsm);
    const int tid = threadIdx.x;
    const int wid = tid >> 5, lane = tid & 31;
    const size_t m0 = (size_t)blockIdx.y * 128;
    const int n0 = blockIdx.x * 128;
    const int wm = (wid & 3) * 32;
    const int wn = (wid >> 2) * 64;

    float acc[2][8][4] = {};
    const int lr = tid >> 1;
    const int lc = (tid & 1) * 16;
    const int am = wm + (lane & 15);
    const int ak = (lane >> 4) * 8;
    const int bn = wn + (lane & 7) + (lane >> 4) * 8;
    const int bk = ((lane >> 3) & 1) * 8;

    auto issue = [&](int c) {
        const int kc = c * BK;
        const int col = (kc >= skip_at) ? kc + skip_amt : kc;
        const size_t oa = (m0 + lr) * (size_t)lda + col + lc;
        const size_t ob = (size_t)(n0 + lr) * ldb + col + lc;
        const uint32_t so = smb + (uint32_t)(c % 3) * SBUF + (uint32_t)(lr * LDSW + lc) * 2;
        CPA16(so + SA_AH, Ah + oa); CPA16(so + SA_AH + 16, Ah + oa + 8);
        CPA16(so + SA_BH, Bh + ob); CPA16(so + SA_BH + 16, Bh + ob + 8);
        CPA16(so + SA_BL, Bl + ob); CPA16(so + SA_BL + 16, Bl + ob + 8);
        CPCOMMIT();
    };

    issue(0);
    if (nchunks > 1) issue(1);
    for (int c = 0; c < nchunks; ++c) {
        if (c + 1 < nchunks) { CPWAIT1(); } else { CPWAIT0(); }
        __syncthreads();
        if (c + 2 < nchunks) issue(c + 2);
        const uint32_t bb = smb + (uint32_t)(c % 3) * SBUF;
#pragma unroll
        for (int k16 = 0; k16 < BK; k16 += 16) {
            uint32_t ahf[2][4], bhf[4][4], blf[4][4];
#pragma unroll
            for (int mi = 0; mi < 2; ++mi) {
                const uint32_t off = bb + (uint32_t)(((am + mi * 16) * LDSW + ak + k16) * 2);
                LDSM4(ahf[mi][0], ahf[mi][1], ahf[mi][2], ahf[mi][3], off + SA_AH);
            }
#pragma unroll
            for (int j = 0; j < 4; ++j) {
                const uint32_t off = bb + (uint32_t)(((bn + j * 16) * LDSW + bk + k16) * 2);
                LDSM4(bhf[j][0], bhf[j][1], bhf[j][2], bhf[j][3], off + SA_BH);
                LDSM4(blf[j][0], blf[j][1], blf[j][2], blf[j][3], off + SA_BL);
            }
#pragma unroll
            for (int mi = 0; mi < 2; ++mi)
#pragma unroll
                for (int j = 0; j < 4; ++j)
#pragma unroll
                    for (int h = 0; h < 2; ++h) {
                        float* d = acc[mi][j * 2 + h];
                        MMA16816(d, ahf[mi], bhf[j][h * 2], bhf[j][h * 2 + 1]);
                        MMA16816(d, ahf[mi], blf[j][h * 2], blf[j][h * 2 + 1]);
                    }
        }
    }
    const int rrow = lane >> 2;
    const int rcol = (lane & 3) * 2;
#pragma unroll
    for (int mi = 0; mi < 2; ++mi)
#pragma unroll
        for (int j = 0; j < 8; ++j) {
            const float* d = acc[mi][j];
            const int n = n0 + wn + j * 8 + rcol;
#pragma unroll
            for (int half = 0; half < 2; ++half) {
                const size_t m = m0 + wm + mi * 16 + rrow + half * 8;
                const float v0 = d[half * 2 + 0], v1 = d[half * 2 + 1];
                if (mode == 0) {
                    *(float2*)(out0 + m * 128 + n) = make_float2(v0, v1);
                } else {
                    if (n < NIN) *(float2*)(out0 + m * NIN + n) = make_float2(v0, v1);
                    else if (n < 576) *(float2*)(out1 + m * NXI + (n - NIN)) = make_float2(v0, v1);
                }
            }
        }
}

// ============ 64x64 GEMM core (fp16 3-product), logical tid + K offset ============
#define LDS2 (BK + 8)
__device__ __forceinline__ void gemm64_core(
    const __half* __restrict__ Ah, const __half* __restrict__ Al,
    const __half* __restrict__ Bh, const __half* __restrict__ Bl,
    int nchunks, int koff, int lda, int ldb, int m0, int n0,
    __half* sAh, __half* sAl, __half* sBh, __half* sBl,
    float acc[2][4][4], int t) {
    const int wid = t >> 5, lane = t & 31;
    const int wm = (wid & 1) * 32;
    const int wn = (wid >> 1) * 32;
    const int lr = t >> 1;
    const int lc = (t & 1) * 16;
    const uint32_t uAh = smem_u32(sAh), uAl = smem_u32(sAl);
    const uint32_t uBh = smem_u32(sBh), uBl = smem_u32(sBl);
    const int am = wm + (lane & 15);
    const int ak = (lane >> 4) * 8;
    const int bn = wn + (lane & 7) + (lane >> 4) * 8;
    const int bk = ((lane >> 3) & 1) * 8;

#pragma unroll
    for (int mi = 0; mi < 2; ++mi)
#pragma unroll
        for (int j = 0; j < 4; ++j)
#pragma unroll
            for (int q = 0; q < 4; ++q) acc[mi][j][q] = 0.0f;

    uint4 pa[2][2], pb[2][2];
    auto gload = [&](int c) {
        const int col = koff + c * BK;
        const size_t oa = (size_t)(m0 + lr) * lda + col + lc;
        const size_t ob = (size_t)(n0 + lr) * ldb + col + lc;
        pa[0][0] = *(const uint4*)(Ah + oa); pa[0][1] = *(const uint4*)(Ah + oa + 8);
        pa[1][0] = *(const uint4*)(Al + oa); pa[1][1] = *(const uint4*)(Al + oa + 8);
        pb[0][0] = *(const uint4*)(Bh + ob); pb[0][1] = *(const uint4*)(Bh + ob + 8);
        pb[1][0] = *(const uint4*)(Bl + ob); pb[1][1] = *(const uint4*)(Bl + ob + 8);
    };

    gload(0);
    for (int c = 0; c < nchunks; ++c) {
        const int so = lr * LDS2 + lc;
        *(uint4*)(sAh + so) = pa[0][0]; *(uint4*)(sAh + so + 8) = pa[0][1];
        *(uint4*)(sAl + so) = pa[1][0]; *(uint4*)(sAl + so + 8) = pa[1][1];
        *(uint4*)(sBh + so) = pb[0][0]; *(uint4*)(sBh + so + 8) = pb[0][1];
        *(uint4*)(sBl + so) = pb[1][0]; *(uint4*)(sBl + so + 8) = pb[1][1];
        __syncthreads();
        if (c + 1 < nchunks) gload(c + 1);
#pragma unroll
        for (int k16 = 0; k16 < BK; k16 += 16) {
            uint32_t ahf[2][4], alf[2][4], bhf[2][4], blf[2][4];
#pragma unroll
            for (int mi = 0; mi < 2; ++mi) {
                const uint32_t off = (uint32_t)(((am + mi * 16) * LDS2 + ak + k16) * 2);
                LDSM4(ahf[mi][0], ahf[mi][1], ahf[mi][2], ahf[mi][3], uAh + off);
                LDSM4(alf[mi][0], alf[mi][1], alf[mi][2], alf[mi][3], uAl + off);
            }
#pragma unroll
            for (int j = 0; j < 2; ++j) {
                const uint32_t off = (uint32_t)(((bn + j * 16) * LDS2 + bk + k16) * 2);
                LDSM4(bhf[j][0], bhf[j][1], bhf[j][2], bhf[j][3], uBh + off);
                LDSM4(blf[j][0], blf[j][1], blf[j][2], blf[j][3], uBl + off);
            }
#pragma unroll
            for (int mi = 0; mi < 2; ++mi)
#pragma unroll
                for (int j = 0; j < 2; ++j)
#pragma unroll
                    for (int h = 0; h < 2; ++h) {
                        float* d = acc[mi][j * 2 + h];
                        MMA16816(d, ahf[mi], bhf[j][h * 2], bhf[j][h * 2 + 1]);
                        MMA16816(d, ahf[mi], blf[j][h * 2], blf[j][h * 2 + 1]);
                        MMA16816(d, alf[mi], bhf[j][h * 2], bhf[j][h * 2 + 1]);
                    }
        }
        __syncthreads();
    }
}

// standalone small GEMM (full H only). emode 0 = fp32 out (+eps diag)
__global__ __launch_bounds__(128) void tc2(
    const __half* __restrict__ Ah, const __half* __restrict__ Al,
    const __half* __restrict__ Bh, const __half* __restrict__ Bl,
    int K, int lda, int ldb,
    float* __restrict__ outf, int ldc, int emode) {
    __shared__ __half sAh[64 * LDS2], sAl[64 * LDS2];
    __shared__ __half sBh[64 * LDS2], sBl[64 * LDS2];
    const int tid = threadIdx.x;
    const int wid = tid >> 5, lane = tid & 31;
    const int m0 = blockIdx.y * 64;
    const int n0 = blockIdx.x * 64;
    const int wm = (wid & 1) * 32;
    const int wn = (wid >> 1) * 32;
    float acc[2][4][4];
    gemm64_core(Ah, Al, Bh, Bl, K / BK, 0, lda, ldb, m0, n0, sAh, sAl, sBh, sBl, acc, tid);

    const int rrow = lane >> 2;
    const int rcol = (lane & 3) * 2;
#pragma unroll
    for (int mi = 0; mi < 2; ++mi)
#pragma unroll
        for (int j = 0; j < 4; ++j) {
            const float* d = acc[mi][j];
            const int n = n0 + wn + j * 8 + rcol;
#pragma unroll
            for (int half = 0; half < 2; ++half) {
                const int m = m0 + wm + mi * 16 + rrow + half * 8;
                float v0 = d[half * 2 + 0], v1 = d[half * 2 + 1];
                if (emode == 0) {
                    if (m == n) v0 += EPSV;
                    if (m == n + 1) v1 += EPSV;
                }
                *(float2*)(outf + (size_t)m * ldc + n) = make_float2(v0, v1);
            }
        }
}

// ============ fused persistent Newton chain + Wout solve tail (128 thr/CTA) ============
#define NWT_BLOCKS 64
__global__ __launch_bounds__(128) void newton_fused() {
    __shared__ __half sAh[64 * LDS2], sAl[64 * LDS2];
    __shared__ __half sBh[64 * LDS2], sBl[64 * LDS2];
    const int tid = threadIdx.x;
    const int wid = tid >> 5, lane = tid & 31;
    const int m0 = (blockIdx.x >> 3) * 64;
    const int n0 = (blockIdx.x & 7) * 64;
    const int wm = (wid & 1) * 32;
    const int wn = (wid >> 1) * 32;
    const int rrow = lane >> 2;
    const int rcol = (lane & 3) * 2;
    float acc[2][4][4];

    int cur = 0;
    for (int it = 0; it < NEWTON_ITERS; ++it) {
        // phase 1: T = M * Z^T -> transposed splits Tt
        gemm64_core(g_MH, g_ML, g_ZTH[cur], g_ZTL[cur], NXI / BK, 0, NXI, NXI, m0, n0,
                    sAh, sAl, sBh, sBl, acc, tid);
#pragma unroll
        for (int mi = 0; mi < 2; ++mi)
#pragma unroll
            for (int j = 0; j < 4; ++j) {
                const float* d = acc[mi][j];
                const int n = n0 + wn + j * 8 + rcol;
#pragma unroll
                for (int half = 0; half < 2; ++half) {
                    const int m = m0 + wm + mi * 16 + rrow + half * 8;
                    split_store(g_TtH, g_TtL, (size_t)n * NXI + m, d[half * 2 + 0]);
                    split_store(g_TtH, g_TtL, (size_t)(n + 1) * NXI + m, d[half * 2 + 1]);
                }
            }
        gridbar(NWT_BLOCKS);

        // phase 2: Zn = 2*Z - Z*T
        gemm64_core(g_ZH[cur], g_ZL[cur], g_TtH, g_TtL, NXI / BK, 0, NXI, NXI, m0, n0,
                    sAh, sAl, sBh, sBl, acc, tid);
        const float* zin = g_Zf[cur];
        float* zout = g_Zf[cur ^ 1];
        const int nx = cur ^ 1;
#pragma unroll
        for (int mi = 0; mi < 2; ++mi)
#pragma unroll
            for (int j = 0; j < 4; ++j) {
                const float* d = acc[mi][j];
                const int n = n0 + wn + j * 8 + rcol;
#pragma unroll
                for (int half = 0; half < 2; ++half) {
                    const int m = m0 + wm + mi * 16 + rrow + half * 8;
                    const size_t o = (size_t)m * NXI + n;
                    float v0 = 2.0f * zin[o] - d[half * 2 + 0];
                    float v1 = 2.0f * zin[o + 1] - d[half * 2 + 1];
                    *(float2*)(zout + o) = make_float2(v0, v1);
                    split_store(g_ZH[nx], g_ZL[nx], o, v0);
                    split_store(g_ZH[nx], g_ZL[nx], o + 1, v1);
                    split_store(g_ZTH[nx], g_ZTL[nx], (size_t)n * NXI + m, v0);
                    split_store(g_ZTH[nx], g_ZTL[nx], (size_t)(n + 1) * NXI + m, v1);
                }
            }
        gridbar(NWT_BLOCKS);
        cur ^= 1;
    }

    // solve tail: Wout[64+m, n] = sum_k Z[m,k] * Rt[n,k]  (96 tiles over 64 CTAs)
    const int fin = NEWTON_ITERS & 1;
    for (int t = blockIdx.x; t < 96; t += NWT_BLOCKS) {
        const int sm0 = (t & 7) * 64;
        const int sn0 = (t >> 3) * 64;
        gemm64_core(g_ZH[fin], g_ZL[fin], g_RtH, g_RtL, NXI / BK, 0, NXI, NXI, sm0, sn0,
                    sAh, sAl, sBh, sBl, acc, tid);
#pragma unroll
        for (int mi = 0; mi < 2; ++mi)
#pragma unroll
            for (int j = 0; j < 4; ++j) {
                const float* d = acc[mi][j];
                const int n = sn0 + wn + j * 8 + rcol;
#pragma unroll
                for (int half = 0; half < 2; ++half) {
                    const int m = sm0 + wm + mi * 16 + rrow + half * 8;
                    const size_t o = (size_t)(64 + m) * 768 + n;
                    split_store(g_WoutH, g_WoutL, o, d[half * 2 + 0]);
                    split_store(g_WoutH, g_WoutL, o + 1, d[half * 2 + 1]);
                }
            }
    }
}

// ---------------- builders ----------------
__global__ void conv_Xt(const float* __restrict__ X) {
    __shared__ float t[32][33];
    const int bx = blockIdx.x * 32, by = blockIdx.y * 32;
    const int tx = threadIdx.x, ty = threadIdx.y;
#pragma unroll
    for (int r = 0; r < 32; r += 8)
        t[ty + r][tx] = X[(size_t)(by + ty + r) * HDIM + bx + tx];
    __syncthreads();
#pragma unroll
    for (int r = 0; r < 32; r += 8) {
        const float v = t[tx][ty + r];
        split_store(g_XtH, g_XtL, (size_t)(bx + ty + r) * HDIM + by + tx, v);
    }
}
// Wpre from g_H: cols 0..511 = -H21, cols 640..767 = D12
__global__ void build_WpreSplit(const float* __restrict__ D12) {
    int idx = blockIdx.x * blockDim.x + threadIdx.x;
    if (idx >= LDIM * 640) return;
    int rr = idx / 640, c = idx - rr * 640;
    float v = (c < NXI) ? -g_H[(size_t)(NXI + rr) * HDIM + c] : D12[rr * NSTATES + (c - NXI)];
    int dc = (c < NXI) ? c : c + 128;
    split_store(g_WpreH, g_WpreL, (size_t)rr * 768 + dc, v);
}
// D11/LamInv from g_H (H22 block; eps already on diag of g_H)
__global__ void build_D11() {
    int idx = blockIdx.x * blockDim.x + threadIdx.x;
    if (idx >= LDIM * LDIM) return;
    int i = idx >> 7, j = idx & 127;
    g_D11[idx] = (j < i) ? -g_H[(size_t)(NXI + i) * HDIM + NXI + j] : 0.0f;
    if (j == i) g_LamInv[i] = 2.0f / g_H[(size_t)(NXI + i) * HDIM + NXI + i];
}
// M = D^-1 E (splits); Z1 = 2a*I - a^2*M ; dinv inline
__global__ void build_MZ(const float* __restrict__ Y) {
    int idx = blockIdx.x * blockDim.x + threadIdx.x;
    if (idx >= NXI * NXI) return;
    int i = idx >> 9, j = idx & 511;
    float dinv = 2.0f / (g_H[(size_t)i * HDIM + i] + g_H[(size_t)(640 + i) * HDIM + 640 + i]);
    float e = 0.5f * (g_H[(size_t)i * HDIM + j] + g_H[(size_t)(640 + i) * HDIM + 640 + j] +
                      Y[(size_t)i * NXI + j] - Y[(size_t)j * NXI + i]);
    float m = dinv * e;
    split_store(g_MH, g_ML, idx, m);
    float z = ((i == j) ? 2.0f * ALPHA : 0.0f) - ALPHA * ALPHA * m;
    g_Zf[0][idx] = z;
    split_store(g_ZH[0], g_ZL[0], idx, z);
    split_store(g_ZTH[0], g_ZTL[0], (size_t)j * NXI + i, z);
}
__global__ void build_Rt(const float* __restrict__ B2) {
    int idx = blockIdx.x * blockDim.x + threadIdx.x;
    if (idx >= NXI * 768) return;
    int i = idx / 768, c = idx - i * 768;
    float dinv = 2.0f / (g_H[(size_t)i * HDIM + i] + g_H[(size_t)(640 + i) * HDIM + 640 + i]);
    float v = (c < 640) ? g_H[(size_t)(640 + i) * HDIM + c] : B2[i * NSTATES + (c - 640)];
    split_store(g_RtH, g_RtL, (size_t)c * NXI + i, dinv * v);
}
__global__ void build_WoutTop(const float* __restrict__ C2, const float* __restrict__ D21,
                              const float* __restrict__ D22) {
    int idx = blockIdx.x * blockDim.x + threadIdx.x;
    if (idx >= NIN * 768) return;
    int rr = idx / 768, c = idx - rr * 768;
    float v = (c < NXI) ? C2[rr * NXI + c]
                        : (c < 640 ? D21[rr * LDIM + (c - NXI)] : D22[rr * NSTATES + (c - 640)]);
    split_store(g_WoutH, g_WoutL, idx, v);
}
__global__ void conv_A(const float* __restrict__ xi, const float* __restrict__ w) {
    size_t idx = (size_t)blockIdx.x * blockDim.x + threadIdx.x;
    size_t b = idx / 160;
    int c0 = (int)(idx - b * 160) * 4;
    if (b >= BATCHN) return;
    float4 v;
    int dc;
    if (c0 < NXI) { v = *(const float4*)(xi + b * NXI + c0); dc = c0; }
    else          { v = *(const float4*)(w + b * NSTATES + (c0 - NXI)); dc = c0 + 128; }
    size_t o = b * 768 + dc;
    split_store(g_AH, g_AL, o + 0, v.x);
    split_store(g_AH, g_AL, o + 1, v.y);
    split_store(g_AH, g_AL, o + 2, v.z);
    split_store(g_AH, g_AL, o + 3, v.w);
}

// ---------------- tanh forward-substitution scan (coalesced split stores) ----------------
__global__ __launch_bounds__(64) void eps_kernel() {
    __shared__ float es[128 * 65];     // stride 65: conflict-free transposed read
    __shared__ float li[128];
    int tid = threadIdx.x;
    size_t b = (size_t)blockIdx.x * 64 + tid;
    for (int i = tid; i < 128; i += 64) li[i] = g_LamInv[i];
    __syncthreads();
    for (int i = 0; i < 128; ++i) {
        float v = g_pre[b * 128 + i];
        const float* __restrict__ dr = &g_D11[i * 128];
        float v0 = 0.f, v1 = 0.f, v2 = 0.f, v3 = 0.f;
        int j = 0;
        for (; j + 3 < i; j += 4) {
            v0 = fmaf(es[(j + 0) * 65 + tid], dr[j + 0], v0);
            v1 = fmaf(es[(j + 1) * 65 + tid], dr[j + 1], v1);
            v2 = fmaf(es[(j + 2) * 65 + tid], dr[j + 2], v2);
            v3 = fmaf(es[(j + 3) * 65 + tid], dr[j + 3], v3);
        }
        for (; j < i; ++j) v0 = fmaf(es[j * 65 + tid], dr[j], v0);
        v += (v0 + v1) + (v2 + v3);
        es[i * 65 + tid] = tanhf(v * li[i]);
    }
    __syncthreads();
    // coalesced split stores: thread t writes cols 512+t and 512+64+t of each row
    const size_t b0 = (size_t)blockIdx.x * 64;
    for (int r = 0; r < 64; ++r) {
        const size_t o = (b0 + r) * 768 + 512;
        split_store(g_AH, g_AL, o + tid, es[tid * 65 + r]);
        split_store(g_AH, g_AL, o + 64 + tid, es[(64 + tid) * 65 + r]);
    }
}

// ---------------- launch ----------------
extern "C" void kernel_launch(void* const* d_in, const int* in_sizes, int n_in,
                              void* d_out, int out_size) {
    (void)in_sizes; (void)n_in; (void)out_size;
    const float* w   = (const float*)d_in[1];
    const float* xi  = (const float*)d_in[2];
    const float* X   = (const float*)d_in[3];
    const float* Y   = (const float*)d_in[4];
    const float* B2  = (const float*)d_in[5];
    const float* C2  = (const float*)d_in[6];
    const float* D21 = (const float*)d_in[7];
    const float* D22 = (const float*)d_in[8];
    const float* D12 = (const float*)d_in[9];
    float* out   = (float*)d_out;
    float* out_u = out;
    float* out_x = out + (size_t)BATCHN * NIN;

    static cudaStream_t s2;
    static cudaEvent_t evStart, evH, evJoin;
    static bool inited = false;
    if (!inited) {
        cudaStreamCreateWithFlags(&s2, cudaStreamNonBlocking);
        cudaEventCreateWithFlags(&evStart, cudaEventDisableTiming);
        cudaEventCreateWithFlags(&evH, cudaEventDisableTiming);
        cudaEventCreateWithFlags(&evJoin, cudaEventDisableTiming);
        cudaFuncSetAttribute(mma_gemm, cudaFuncAttributeMaxDynamicSharedMemorySize, 3 * SBUF);
        inited = true;
    }

    float *pH, *pPre;
    __half *pAH, *pWpreH, *pWpreL, *pWoutH, *pWoutL, *pXtH, *pXtL;
    cudaGetSymbolAddress((void**)&pH, g_H);
    cudaGetSymbolAddress((void**)&pPre, g_pre);
    cudaGetSymbolAddress((void**)&pAH, g_AH);
    cudaGetSymbolAddress((void**)&pWpreH, g_WpreH);
    cudaGetSymbolAddress((void**)&pWpreL, g_WpreL);
    cudaGetSymbolAddress((void**)&pWoutH, g_WoutH);
    cudaGetSymbolAddress((void**)&pWoutL, g_WoutL);
    cudaGetSymbolAddress((void**)&pXtH, g_XtH);
    cudaGetSymbolAddress((void**)&pXtL, g_XtL);

    // ---- top fork: conv_A on s2 in parallel with Xt/H on s0 ----
    cudaEventRecord(evStart, 0);
    cudaStreamWaitEvent(s2, evStart, 0);
    conv_A<<<(BATCHN * 160 + 255) / 256, 256, 0, s2>>>(xi, w);

    conv_Xt<<<dim3(HDIM / 32, HDIM / 32), dim3(32, 8)>>>(X);
    tc2<<<dim3(HDIM / 64, HDIM / 64), 128>>>(
        pXtH, pXtL, pXtH, pXtL, HDIM, HDIM, HDIM, pH, HDIM, 0);
    cudaEventRecord(evH, 0);
    cudaStreamWaitEvent(s2, evH, 0);

    // ---- branch A (s2): Wpre/D11 from H -> pre-GEMM (2-product) -> eps ----
    build_WpreSplit<<<(LDIM * 640 + 255) / 256, 256, 0, s2>>>(D12);
    build_D11<<<(LDIM * LDIM + 255) / 256, 256, 0, s2>>>();
    mma_gemm<<<dim3(1, BATCHN / 128), 256, 3 * SBUF, s2>>>(
        pAH, pWpreH, pWpreL, 20, 512, 128, 768, 768, pPre, nullptr, 0);
    eps_kernel<<<BATCHN / 64, 64, 0, s2>>>();
    cudaEventRecord(evJoin, s2);

    // ---- branch B (s0): MZ/Rt/WoutTop -> fused Newton + solve tail ----
    build_MZ<<<(NXI * NXI + 255) / 256, 256>>>(Y);
    build_Rt<<<(NXI * 768 + 255) / 256, 256>>>(B2);
    build_WoutTop<<<(NIN * 768 + 255) / 256, 256>>>(C2, D21, D22);
    newton_fused<<<NWT_BLOCKS, 128>>>();

    // ---- join ----
    cudaStreamWaitEvent(0, evJoin, 0);

    // [u | xi_] = [xi|eps|w] @ Wout^T  (2-product fp16 split)
    mma_gemm<<<dim3(5, BATCHN / 128), 256, 3 * SBUF>>>(
        pAH, pWoutH, pWoutL, 24, 1 << 30, 0, 768, 768, out_u, out_x, 1);
}

// round 14
// speedup vs baseline: 1.3054x; 1.2292x over previous
#include <cuda_runtime.h>
#include <cuda_fp16.h>
#include <math.h>
#include <stdint.h>

#define NXI 512
#define LDIM 128
#define NSTATES 128
#define NIN 64
#define HDIM 1152           // 2*NXI + LDIM
#define BATCHN 32768
#define EPSV 0.001f
#define ALPHA 0.55f
#define NEWTON_ITERS 7      // + fused first step = 8 squarings

// ---------------- device scratch ----------------
__device__ float g_H[HDIM * HDIM];
__device__ float g_Zf[2][NXI * NXI];
__device__ float g_D11[LDIM * LDIM];
__device__ float g_LamInv[LDIM];
__device__ float g_pre[(size_t)BATCHN * LDIM];
__device__ unsigned g_barcnt, g_barep;     // software grid barrier state (zero-init)

// split-fp16 operand arrays
__device__ __half g_AH[(size_t)BATCHN * 768];   // [xi | eps | w]
__device__ __half g_AL[(size_t)BATCHN * 768];
__device__ __half g_WpreH[LDIM * 768];
__device__ __half g_WpreL[LDIM * 768];
__device__ __half g_WoutH[640 * 768];           // rows 576..639 stay zero
__device__ __half g_WoutL[640 * 768];
__device__ __half g_XtH[HDIM * HDIM];
__device__ __half g_XtL[HDIM * HDIM];
__device__ __half g_MH[NXI * NXI], g_ML[NXI * NXI];
__device__ __half g_ZH[2][NXI * NXI], g_ZL[2][NXI * NXI];
__device__ __half g_ZTH[2][NXI * NXI], g_ZTL[2][NXI * NXI];
__device__ __half g_TtH[NXI * NXI], g_TtL[NXI * NXI];
__device__ __half g_RtH[768 * NXI], g_RtL[768 * NXI];

// ---------------- PTX helpers ----------------
__device__ __forceinline__ uint32_t smem_u32(const void* p) {
    uint32_t a;
    asm("{ .reg .u64 t; cvta.to.shared.u64 t, %1; cvt.u32.u64 %0, t; }" : "=r"(a) : "l"(p));
    return a;
}
#define LDSM4(r0, r1, r2, r3, addr) \
    asm volatile("ldmatrix.sync.aligned.m8n8.x4.shared.b16 {%0,%1,%2,%3}, [%4];" \
                 : "=r"(r0), "=r"(r1), "=r"(r2), "=r"(r3) : "r"(addr))
#define MMA16816(d, a, b0, b1) \
    asm volatile("mma.sync.aligned.m16n8k16.row.col.f32.f16.f16.f32 " \
                 "{%0,%1,%2,%3},{%4,%5,%6,%7},{%8,%9},{%0,%1,%2,%3};" \
                 : "+f"(d[0]), "+f"(d[1]), "+f"(d[2]), "+f"(d[3]) \
                 : "r"(a[0]), "r"(a[1]), "r"(a[2]), "r"(a[3]), "r"(b0), "r"(b1))
#define CPA16(smaddr, gptr) \
    asm volatile("cp.async.cg.shared.global [%0], [%1], 16;" :: "r"(smaddr), "l"(gptr))
#define CPCOMMIT() asm volatile("cp.async.commit_group;" ::: "memory")
#define CPWAIT1()  asm volatile("cp.async.wait_group 1;" ::: "memory")
#define CPWAIT0()  asm volatile("cp.async.wait_group 0;" ::: "memory")

__device__ __forceinline__ void split_store(__half* H, __half* L, size_t idx, float v) {
    __half h = __float2half(v);
    H[idx] = h;
    L[idx] = __float2half(v - __half2float(h));
}

// software grid barrier (all NBLK CTAs co-resident). Replay-safe.
__device__ __forceinline__ void gridbar(int nblk) {
    __threadfence();
    __syncthreads();
    if (threadIdx.x == 0) {
        unsigned e = ((volatile unsigned*)&g_barep)[0];
        unsigned t = atomicAdd(&g_barcnt, 1);
        if (t == (unsigned)nblk - 1) {
            g_barcnt = 0;
            __threadfence();
            atomicAdd(&g_barep, 1);
        } else {
            while (((volatile unsigned*)&g_barep)[0] == e) {}
        }
    }
    __syncthreads();
    __threadfence();
}

// ============ big batch GEMM (128x128 tiles, cp.async 3-stage, 1 sync/chunk) ============
#define BK 32
#define LDSW (BK + 8)
#define SA_AH 0u
#define SA_BH 10240u
#define SA_BL 20480u
#define SBUF  30720u
__global__ __launch_bounds__(256) void mma_gemm(
    const __half* __restrict__ Ah,
    const __half* __restrict__ Bh, const __half* __restrict__ Bl,
    int nchunks, int skip_at, int skip_amt, int lda, int ldb,
    float* __restrict__ out0, float* __restrict__ out1, int mode) {
    extern __shared__ char dsm[];
    const uint32_t smb = smem_u32(dsm);
    const int tid = threadIdx.x;
    const int wid = tid >> 5, lane = tid & 31;
    const size_t m0 = (size_t)blockIdx.y * 128;
    const int n0 = blockIdx.x * 128;
    const int wm = (wid & 3) * 32;
    const int wn = (wid >> 2) * 64;

    float acc[2][8][4] = {};
    const int lr = tid >> 1;
    const int lc = (tid & 1) * 16;
    const int am = wm + (lane & 15);
    const int ak = (lane >> 4) * 8;
    const int bn = wn + (lane & 7) + (lane >> 4) * 8;
    const int bk = ((lane >> 3) & 1) * 8;

    auto issue = [&](int c) {
        const int kc = c * BK;
        const int col = (kc >= skip_at) ? kc + skip_amt : kc;
        const size_t oa = (m0 + lr) * (size_t)lda + col + lc;
        const size_t ob = (size_t)(n0 + lr) * ldb + col + lc;
        const uint32_t so = smb + (uint32_t)(c % 3) * SBUF + (uint32_t)(lr * LDSW + lc) * 2;
        CPA16(so + SA_AH, Ah + oa); CPA16(so + SA_AH + 16, Ah + oa + 8);
        CPA16(so + SA_BH, Bh + ob); CPA16(so + SA_BH + 16, Bh + ob + 8);
        CPA16(so + SA_BL, Bl + ob); CPA16(so + SA_BL + 16, Bl + ob + 8);
        CPCOMMIT();
    };

    issue(0);
    if (nchunks > 1) issue(1);
    for (int c = 0; c < nchunks; ++c) {
        if (c + 1 < nchunks) { CPWAIT1(); } else { CPWAIT0(); }
        __syncthreads();
        if (c + 2 < nchunks) issue(c + 2);
        const uint32_t bb = smb + (uint32_t)(c % 3) * SBUF;
#pragma unroll
        for (int k16 = 0; k16 < BK; k16 += 16) {
            uint32_t ahf[2][4], bhf[4][4], blf[4][4];
#pragma unroll
            for (int mi = 0; mi < 2; ++mi) {
                const uint32_t off = bb + (uint32_t)(((am + mi * 16) * LDSW + ak + k16) * 2);
                LDSM4(ahf[mi][0], ahf[mi][1], ahf[mi][2], ahf[mi][3], off + SA_AH);
            }
#pragma unroll
            for (int j = 0; j < 4; ++j) {
                const uint32_t off = bb + (uint32_t)(((bn + j * 16) * LDSW + bk + k16) * 2);
                LDSM4(bhf[j][0], bhf[j][1], bhf[j][2], bhf[j][3], off + SA_BH);
                LDSM4(blf[j][0], blf[j][1], blf[j][2], blf[j][3], off + SA_BL);
            }
#pragma unroll
            for (int mi = 0; mi < 2; ++mi)
#pragma unroll
                for (int j = 0; j < 4; ++j)
#pragma unroll
                    for (int h = 0; h < 2; ++h) {
                        float* d = acc[mi][j * 2 + h];
                        MMA16816(d, ahf[mi], bhf[j][h * 2], bhf[j][h * 2 + 1]);
                        MMA16816(d, ahf[mi], blf[j][h * 2], blf[j][h * 2 + 1]);
                    }
        }
    }
    const int rrow = lane >> 2;
    const int rcol = (lane & 3) * 2;
#pragma unroll
    for (int mi = 0; mi < 2; ++mi)
#pragma unroll
        for (int j = 0; j < 8; ++j) {
            const float* d = acc[mi][j];
            const int n = n0 + wn + j * 8 + rcol;
#pragma unroll
            for (int half = 0; half < 2; ++half) {
                const size_t m = m0 + wm + mi * 16 + rrow + half * 8;
                const float v0 = d[half * 2 + 0], v1 = d[half * 2 + 1];
                if (mode == 0) {
                    *(float2*)(out0 + m * 128 + n) = make_float2(v0, v1);
                } else {
                    if (n < NIN) *(float2*)(out0 + m * NIN + n) = make_float2(v0, v1);
                    else if (n < 576) *(float2*)(out1 + m * NXI + (n - NIN)) = make_float2(v0, v1);
                }
            }
        }
}

// ============ 64x64 GEMM core (fp16 3-product), logical tid + K offset ============
#define LDS2 (BK + 8)
__device__ __forceinline__ void gemm64_core(
    const __half* __restrict__ Ah, const __half* __restrict__ Al,
    const __half* __restrict__ Bh, const __half* __restrict__ Bl,
    int nchunks, int koff, int lda, int ldb, int m0, int n0,
    __half* sAh, __half* sAl, __half* sBh, __half* sBl,
    float acc[2][4][4], int t) {
    const int wid = t >> 5, lane = t & 31;
    const int wm = (wid & 1) * 32;
    const int wn = (wid >> 1) * 32;
    const int lr = t >> 1;
    const int lc = (t & 1) * 16;
    const uint32_t uAh = smem_u32(sAh), uAl = smem_u32(sAl);
    const uint32_t uBh = smem_u32(sBh), uBl = smem_u32(sBl);
    const int am = wm + (lane & 15);
    const int ak = (lane >> 4) * 8;
    const int bn = wn + (lane & 7) + (lane >> 4) * 8;
    const int bk = ((lane >> 3) & 1) * 8;

#pragma unroll
    for (int mi = 0; mi < 2; ++mi)
#pragma unroll
        for (int j = 0; j < 4; ++j)
#pragma unroll
            for (int q = 0; q < 4; ++q) acc[mi][j][q] = 0.0f;

    uint4 pa[2][2], pb[2][2];
    auto gload = [&](int c) {
        const int col = koff + c * BK;
        const size_t oa = (size_t)(m0 + lr) * lda + col + lc;
        const size_t ob = (size_t)(n0 + lr) * ldb + col + lc;
        pa[0][0] = *(const uint4*)(Ah + oa); pa[0][1] = *(const uint4*)(Ah + oa + 8);
        pa[1][0] = *(const uint4*)(Al + oa); pa[1][1] = *(const uint4*)(Al + oa + 8);
        pb[0][0] = *(const uint4*)(Bh + ob); pb[0][1] = *(const uint4*)(Bh + ob + 8);
        pb[1][0] = *(const uint4*)(Bl + ob); pb[1][1] = *(const uint4*)(Bl + ob + 8);
    };

    gload(0);
    for (int c = 0; c < nchunks; ++c) {
        const int so = lr * LDS2 + lc;
        *(uint4*)(sAh + so) = pa[0][0]; *(uint4*)(sAh + so + 8) = pa[0][1];
        *(uint4*)(sAl + so) = pa[1][0]; *(uint4*)(sAl + so + 8) = pa[1][1];
        *(uint4*)(sBh + so) = pb[0][0]; *(uint4*)(sBh + so + 8) = pb[0][1];
        *(uint4*)(sBl + so) = pb[1][0]; *(uint4*)(sBl + so + 8) = pb[1][1];
        __syncthreads();
        if (c + 1 < nchunks) gload(c + 1);
#pragma unroll
        for (int k16 = 0; k16 < BK; k16 += 16) {
            uint32_t ahf[2][4], alf[2][4], bhf[2][4], blf[2][4];
#pragma unroll
            for (int mi = 0; mi < 2; ++mi) {
                const uint32_t off = (uint32_t)(((am + mi * 16) * LDS2 + ak + k16) * 2);
                LDSM4(ahf[mi][0], ahf[mi][1], ahf[mi][2], ahf[mi][3], uAh + off);
                LDSM4(alf[mi][0], alf[mi][1], alf[mi][2], alf[mi][3], uAl + off);
            }
#pragma unroll
            for (int j = 0; j < 2; ++j) {
                const uint32_t off = (uint32_t)(((bn + j * 16) * LDS2 + bk + k16) * 2);
                LDSM4(bhf[j][0], bhf[j][1], bhf[j][2], bhf[j][3], uBh + off);
                LDSM4(blf[j][0], blf[j][1], blf[j][2], blf[j][3], uBl + off);
            }
#pragma unroll
            for (int mi = 0; mi < 2; ++mi)
#pragma unroll
                for (int j = 0; j < 2; ++j)
#pragma unroll
                    for (int h = 0; h < 2; ++h) {
                        float* d = acc[mi][j * 2 + h];
                        MMA16816(d, ahf[mi], bhf[j][h * 2], bhf[j][h * 2 + 1]);
                        MMA16816(d, ahf[mi], blf[j][h * 2], blf[j][h * 2 + 1]);
                        MMA16816(d, alf[mi], bhf[j][h * 2], bhf[j][h * 2 + 1]);
                    }
        }
        __syncthreads();
    }
}

// H GEMM over the 228 needed tiles only (1-D tile list)
__global__ __launch_bounds__(128) void tc2H(
    const __half* __restrict__ Ah, const __half* __restrict__ Al) {
    __shared__ __half sAh[64 * LDS2], sAl[64 * LDS2];
    __shared__ __half sBh[64 * LDS2], sBl[64 * LDS2];
    const int tid = threadIdx.x;
    const int wid = tid >> 5, lane = tid & 31;
    int b = blockIdx.x, m0, n0;
    if (b < 64)       { m0 = (b >> 3) * 64;          n0 = (b & 7) * 64; }           // H11
    else if (b < 84)  { int t = b - 64; m0 = 512 + (t / 10) * 64; n0 = (t % 10) * 64; } // H21|H22
    else              { int t = b - 84; m0 = 640 + (t / 18) * 64; n0 = (t % 18) * 64; } // bottom band
    const int wm = (wid & 1) * 32;
    const int wn = (wid >> 1) * 32;
    float acc[2][4][4];
    gemm64_core(Ah, Al, Ah, Al, HDIM / BK, 0, HDIM, HDIM, m0, n0, sAh, sAl, sBh, sBl, acc, tid);

    const int rrow = lane >> 2;
    const int rcol = (lane & 3) * 2;
#pragma unroll
    for (int mi = 0; mi < 2; ++mi)
#pragma unroll
        for (int j = 0; j < 4; ++j) {
            const float* d = acc[mi][j];
            const int n = n0 + wn + j * 8 + rcol;
#pragma unroll
            for (int half = 0; half < 2; ++half) {
                const int m = m0 + wm + mi * 16 + rrow + half * 8;
                float v0 = d[half * 2 + 0], v1 = d[half * 2 + 1];
                if (m == n) v0 += EPSV;
                if (m == n + 1) v1 += EPSV;
                *(float2*)(g_H + (size_t)m * HDIM + n) = make_float2(v0, v1);
            }
        }
}

// ============ fused persistent Newton (k-split 256-thr, proven in R12) + solve tail ============
#define NWT_BLOCKS 64
__global__ __launch_bounds__(256) void newton_fused() {
    __shared__ __half smt[8][64 * LDS2];       // 40 KB: 4 tile buffers per warpgroup
    const int tid = threadIdx.x;
    const int wg = tid >> 7;                   // warpgroup 0/1 = K halves
    const int wt = tid & 127;
    __half* bAh = smt[wg * 4 + 0];
    __half* bAl = smt[wg * 4 + 1];
    __half* bBh = smt[wg * 4 + 2];
    __half* bBl = smt[wg * 4 + 3];
    float* red = (float*)smt;                  // scratch reused after tiles drain
    const int m0 = (blockIdx.x >> 3) * 64;
    const int n0 = (blockIdx.x & 7) * 64;
    const int wid = wt >> 5, lane = wt & 31;
    const int wm = (wid & 1) * 32;
    const int wn = (wid >> 1) * 32;
    const int rrow = lane >> 2;
    const int rcol = (lane & 3) * 2;
    float acc[2][4][4];

    auto half_gemm = [&](const __half* Ah, const __half* Al,
                         const __half* Bh, const __half* Bl, int tm0, int tn0) {
        gemm64_core(Ah, Al, Bh, Bl, (NXI / BK) / 2, wg * (NXI / 2), NXI, NXI,
                    tm0, tn0, bAh, bAl, bBh, bBl, acc, wt);
        if (wg == 1) {
            float* dst = red + wt * 32;
#pragma unroll
            for (int mi = 0; mi < 2; ++mi)
#pragma unroll
                for (int j = 0; j < 4; ++j)
#pragma unroll
                    for (int q = 0; q < 4; ++q)
                        dst[(mi * 4 + j) * 4 + q] = acc[mi][j][q];
        }
        __syncthreads();
        if (wg == 0) {
            const float* src = red + wt * 32;
#pragma unroll
            for (int mi = 0; mi < 2; ++mi)
#pragma unroll
                for (int j = 0; j < 4; ++j)
#pragma unroll
                    for (int q = 0; q < 4; ++q)
                        acc[mi][j][q] += src[(mi * 4 + j) * 4 + q];
        }
        __syncthreads();
    };

    int cur = 0;
    for (int it = 0; it < NEWTON_ITERS; ++it) {
        half_gemm(g_MH, g_ML, g_ZTH[cur], g_ZTL[cur], m0, n0);
        if (wg == 0) {
#pragma unroll
            for (int mi = 0; mi < 2; ++mi)
#pragma unroll
                for (int j = 0; j < 4; ++j) {
                    const float* d = acc[mi][j];
                    const int n = n0 + wn + j * 8 + rcol;
#pragma unroll
                    for (int half = 0; half < 2; ++half) {
                        const int m = m0 + wm + mi * 16 + rrow + half * 8;
                        split_store(g_TtH, g_TtL, (size_t)n * NXI + m, d[half * 2 + 0]);
                        split_store(g_TtH, g_TtL, (size_t)(n + 1) * NXI + m, d[half * 2 + 1]);
                    }
                }
        }
        gridbar(NWT_BLOCKS);

        half_gemm(g_ZH[cur], g_ZL[cur], g_TtH, g_TtL, m0, n0);
        if (wg == 0) {
            const float* zin = g_Zf[cur];
            float* zout = g_Zf[cur ^ 1];
            const int nx = cur ^ 1;
#pragma unroll
            for (int mi = 0; mi < 2; ++mi)
#pragma unroll
                for (int j = 0; j < 4; ++j) {
                    const float* d = acc[mi][j];
                    const int n = n0 + wn + j * 8 + rcol;
#pragma unroll
                    for (int half = 0; half < 2; ++half) {
                        const int m = m0 + wm + mi * 16 + rrow + half * 8;
                        const size_t o = (size_t)m * NXI + n;
                        float v0 = 2.0f * zin[o] - d[half * 2 + 0];
                        float v1 = 2.0f * zin[o + 1] - d[half * 2 + 1];
                        *(float2*)(zout + o) = make_float2(v0, v1);
                        split_store(g_ZH[nx], g_ZL[nx], o, v0);
                        split_store(g_ZH[nx], g_ZL[nx], o + 1, v1);
                        split_store(g_ZTH[nx], g_ZTL[nx], (size_t)n * NXI + m, v0);
                        split_store(g_ZTH[nx], g_ZTL[nx], (size_t)(n + 1) * NXI + m, v1);
                    }
                }
        }
        gridbar(NWT_BLOCKS);
        cur ^= 1;
    }

    // solve tail: Wout[64+m, n] = sum_k Z[m,k] * Rt[n,k]
    const int fin = NEWTON_ITERS & 1;
    for (int t = blockIdx.x; t < 96; t += NWT_BLOCKS) {
        const int sm0 = (t & 7) * 64;
        const int sn0 = (t >> 3) * 64;
        half_gemm(g_ZH[fin], g_ZL[fin], g_RtH, g_RtL, sm0, sn0);
        if (wg == 0) {
#pragma unroll
            for (int mi = 0; mi < 2; ++mi)
#pragma unroll
                for (int j = 0; j < 4; ++j) {
                    const float* d = acc[mi][j];
                    const int n = sn0 + wn + j * 8 + rcol;
#pragma unroll
                    for (int half = 0; half < 2; ++half) {
                        const int m = sm0 + wm + mi * 16 + rrow + half * 8;
                        const size_t o = (size_t)(64 + m) * 768 + n;
                        split_store(g_WoutH, g_WoutL, o, d[half * 2 + 0]);
                        split_store(g_WoutH, g_WoutL, o + 1, d[half * 2 + 1]);
                    }
                }
        }
    }
}

// ---------------- builders ----------------
__global__ void conv_Xt(const float* __restrict__ X) {
    __shared__ float t[32][33];
    const int bx = blockIdx.x * 32, by = blockIdx.y * 32;
    const int tx = threadIdx.x, ty = threadIdx.y;
#pragma unroll
    for (int r = 0; r < 32; r += 8)
        t[ty + r][tx] = X[(size_t)(by + ty + r) * HDIM + bx + tx];
    __syncthreads();
#pragma unroll
    for (int r = 0; r < 32; r += 8) {
        const float v = t[tx][ty + r];
        split_store(g_XtH, g_XtL, (size_t)(bx + ty + r) * HDIM + by + tx, v);
    }
}
__global__ void build_WpreSplit(const float* __restrict__ D12) {
    int idx = blockIdx.x * blockDim.x + threadIdx.x;
    if (idx >= LDIM * 640) return;
    int rr = idx / 640, c = idx - rr * 640;
    float v = (c < NXI) ? -g_H[(size_t)(NXI + rr) * HDIM + c] : D12[rr * NSTATES + (c - NXI)];
    int dc = (c < NXI) ? c : c + 128;
    split_store(g_WpreH, g_WpreL, (size_t)rr * 768 + dc, v);
}
__global__ void build_D11() {
    int idx = blockIdx.x * blockDim.x + threadIdx.x;
    if (idx >= LDIM * LDIM) return;
    int i = idx >> 7, j = idx & 127;
    g_D11[idx] = (j < i) ? -g_H[(size_t)(NXI + i) * HDIM + NXI + j] : 0.0f;
    if (j == i) g_LamInv[i] = 2.0f / g_H[(size_t)(NXI + i) * HDIM + NXI + i];
}
// merged: MZ (0..262143), Rt (..655359), WoutTop (..704511)
__global__ void build_all(const float* __restrict__ Y, const float* __restrict__ B2,
                          const float* __restrict__ C2, const float* __restrict__ D21,
                          const float* __restrict__ D22) {
    int idx = blockIdx.x * blockDim.x + threadIdx.x;
    if (idx < NXI * NXI) {
        int i = idx >> 9, j = idx & 511;
        float dinv = 2.0f / (g_H[(size_t)i * HDIM + i] + g_H[(size_t)(640 + i) * HDIM + 640 + i]);
        float e = 0.5f * (g_H[(size_t)i * HDIM + j] + g_H[(size_t)(640 + i) * HDIM + 640 + j] +
                          Y[(size_t)i * NXI + j] - Y[(size_t)j * NXI + i]);
        float m = dinv * e;
        split_store(g_MH, g_ML, idx, m);
        float z = ((i == j) ? 2.0f * ALPHA : 0.0f) - ALPHA * ALPHA * m;
        g_Zf[0][idx] = z;
        split_store(g_ZH[0], g_ZL[0], idx, z);
        split_store(g_ZTH[0], g_ZTL[0], (size_t)j * NXI + i, z);
    } else if (idx < NXI * NXI + NXI * 768) {
        int t = idx - NXI * NXI;
        int i = t / 768, c = t - i * 768;
        float dinv = 2.0f / (g_H[(size_t)i * HDIM + i] + g_H[(size_t)(640 + i) * HDIM + 640 + i]);
        float v = (c < 640) ? g_H[(size_t)(640 + i) * HDIM + c] : B2[i * NSTATES + (c - 640)];
        split_store(g_RtH, g_RtL, (size_t)c * NXI + i, dinv * v);
    } else if (idx < NXI * NXI + NXI * 768 + NIN * 768) {
        int t = idx - NXI * NXI - NXI * 768;
        int rr = t / 768, c = t - rr * 768;
        float v = (c < NXI) ? C2[rr * NXI + c]
                            : (c < 640 ? D21[rr * LDIM + (c - NXI)] : D22[rr * NSTATES + (c - 640)]);
        split_store(g_WoutH, g_WoutL, t, v);
    }
}
__global__ void conv_A(const float* __restrict__ xi, const float* __restrict__ w) {
    size_t idx = (size_t)blockIdx.x * blockDim.x + threadIdx.x;
    size_t b = idx / 160;
    int c0 = (int)(idx - b * 160) * 4;
    if (b >= BATCHN) return;
    float4 v;
    int dc;
    if (c0 < NXI) { v = *(const float4*)(xi + b * NXI + c0); dc = c0; }
    else          { v = *(const float4*)(w + b * NSTATES + (c0 - NXI)); dc = c0 + 128; }
    size_t o = b * 768 + dc;
    split_store(g_AH, g_AL, o + 0, v.x);
    split_store(g_AH, g_AL, o + 1, v.y);
    split_store(g_AH, g_AL, o + 2, v.z);
    split_store(g_AH, g_AL, o + 3, v.w);
}

// ---------------- tanh forward-substitution scan (coalesced split stores) ----------------
__global__ __launch_bounds__(64) void eps_kernel() {
    __shared__ float es[128 * 65];
    __shared__ float li[128];
    int tid = threadIdx.x;
    size_t b = (size_t)blockIdx.x * 64 + tid;
    for (int i = tid; i < 128; i += 64) li[i] = g_LamInv[i];
    __syncthreads();
    for (int i = 0; i < 128; ++i) {
        float v = g_pre[b * 128 + i];
        const float* __restrict__ dr = &g_D11[i * 128];
        float v0 = 0.f, v1 = 0.f, v2 = 0.f, v3 = 0.f;
        int j = 0;
        for (; j + 3 < i; j += 4) {
            v0 = fmaf(es[(j + 0) * 65 + tid], dr[j + 0], v0);
            v1 = fmaf(es[(j + 1) * 65 + tid], dr[j + 1], v1);
            v2 = fmaf(es[(j + 2) * 65 + tid], dr[j + 2], v2);
            v3 = fmaf(es[(j + 3) * 65 + tid], dr[j + 3], v3);
        }
        for (; j < i; ++j) v0 = fmaf(es[j * 65 + tid], dr[j], v0);
        v += (v0 + v1) + (v2 + v3);
        es[i * 65 + tid] = tanhf(v * li[i]);
    }
    __syncthreads();
    const size_t b0 = (size_t)blockIdx.x * 64;
    for (int r = 0; r < 64; ++r) {
        const size_t o = (b0 + r) * 768 + 512;
        split_store(g_AH, g_AL, o + tid, es[tid * 65 + r]);
        split_store(g_AH, g_AL, o + 64 + tid, es[(64 + tid) * 65 + r]);
    }
}

// ---------------- launch ----------------
extern "C" void kernel_launch(void* const* d_in, const int* in_sizes, int n_in,
                              void* d_out, int out_size) {
    (void)in_sizes; (void)n_in; (void)out_size;
    const float* w   = (const float*)d_in[1];
    const float* xi  = (const float*)d_in[2];
    const float* X   = (const float*)d_in[3];
    const float* Y   = (const float*)d_in[4];
    const float* B2  = (const float*)d_in[5];
    const float* C2  = (const float*)d_in[6];
    const float* D21 = (const float*)d_in[7];
    const float* D22 = (const float*)d_in[8];
    const float* D12 = (const float*)d_in[9];
    float* out   = (float*)d_out;
    float* out_u = out;
    float* out_x = out + (size_t)BATCHN * NIN;

    static cudaStream_t s2;
    static cudaEvent_t evStart, evH, evJoin;
    static bool inited = false;
    if (!inited) {
        cudaStreamCreateWithFlags(&s2, cudaStreamNonBlocking);
        cudaEventCreateWithFlags(&evStart, cudaEventDisableTiming);
        cudaEventCreateWithFlags(&evH, cudaEventDisableTiming);
        cudaEventCreateWithFlags(&evJoin, cudaEventDisableTiming);
        cudaFuncSetAttribute(mma_gemm, cudaFuncAttributeMaxDynamicSharedMemorySize, 3 * SBUF);
        inited = true;
    }

    float* pPre;
    __half *pAH, *pWpreH, *pWpreL, *pWoutH, *pWoutL, *pXtH, *pXtL;
    cudaGetSymbolAddress((void**)&pPre, g_pre);
    cudaGetSymbolAddress((void**)&pAH, g_AH);
    cudaGetSymbolAddress((void**)&pWpreH, g_WpreH);
    cudaGetSymbolAddress((void**)&pWpreL, g_WpreL);
    cudaGetSymbolAddress((void**)&pWoutH, g_WoutH);
    cudaGetSymbolAddress((void**)&pWoutL, g_WoutL);
    cudaGetSymbolAddress((void**)&pXtH, g_XtH);
    cudaGetSymbolAddress((void**)&pXtL, g_XtL);

    // ---- top fork: conv_A on s2 in parallel with Xt/H on s0 ----
    cudaEventRecord(evStart, 0);
    cudaStreamWaitEvent(s2, evStart, 0);
    conv_A<<<(BATCHN * 160 + 255) / 256, 256, 0, s2>>>(xi, w);

    conv_Xt<<<dim3(HDIM / 32, HDIM / 32), dim3(32, 8)>>>(X);
    tc2H<<<228, 128>>>(pXtH, pXtL);
    cudaEventRecord(evH, 0);
    cudaStreamWaitEvent(s2, evH, 0);

    // ---- branch A (s2): Wpre/D11 from H -> pre-GEMM (2-product) -> eps ----
    build_WpreSplit<<<(LDIM * 640 + 255) / 256, 256, 0, s2>>>(D12);
    build_D11<<<(LDIM * LDIM + 255) / 256, 256, 0, s2>>>();
    mma_gemm<<<dim3(1, BATCHN / 128), 256, 3 * SBUF, s2>>>(
        pAH, pWpreH, pWpreL, 20, 512, 128, 768, 768, pPre, nullptr, 0);
    eps_kernel<<<BATCHN / 64, 64, 0, s2>>>();
    cudaEventRecord(evJoin, s2);

    // ---- branch B (s0): merged builders -> fused Newton (k-split) + solve tail ----
    build_all<<<(704512 + 255) / 256, 256>>>(Y, B2, C2, D21, D22);
    newton_fused<<<NWT_BLOCKS, 256>>>();

    // ---- join ----
    cudaStreamWaitEvent(0, evJoin, 0);

    // [u | xi_] = [xi|eps|w] @ Wout^T  (2-product fp16 split)
    mma_gemm<<<dim3(5, BATCHN / 128), 256, 3 * SBUF>>>(
        pAH, pWoutH, pWoutL, 24, 1 << 30, 0, 768, 768, out_u, out_x, 1);
}

// round 15
// speedup vs baseline: 1.5170x; 1.1621x over previous
#include <cuda_runtime.h>
#include <cuda_fp16.h>
#include <math.h>
#include <stdint.h>

#define NXI 512
#define LDIM 128
#define NSTATES 128
#define NIN 64
#define HDIM 1152           // 2*NXI + LDIM
#define BATCHN 32768
#define EPSV 0.001f
#define ALPHA 0.55f
#define NEWTON_ITERS 7      // + fused first step = 8 squarings

// ---------------- device scratch ----------------
__device__ float g_H[HDIM * HDIM];
__device__ float g_Zf[2][NXI * NXI];
__device__ float g_D11[LDIM * LDIM];
__device__ float g_LamInv[LDIM];
__device__ float g_pre[(size_t)BATCHN * LDIM];
__device__ unsigned g_barcnt, g_barep;     // software grid barrier state (zero-init)

// split-fp16 operand arrays
__device__ __half g_AH[(size_t)BATCHN * 768];   // [xi | eps | w]
__device__ __half g_AL[(size_t)BATCHN * 768];
__device__ __half g_WpreH[LDIM * 768];
__device__ __half g_WpreL[LDIM * 768];
__device__ __half g_WoutH[640 * 768];           // rows 576..639 stay zero
__device__ __half g_WoutL[640 * 768];
__device__ __half g_XtH[HDIM * HDIM];
__device__ __half g_XtL[HDIM * HDIM];
__device__ __half g_MH[NXI * NXI], g_ML[NXI * NXI];
__device__ __half g_ZH[2][NXI * NXI], g_ZL[2][NXI * NXI];
__device__ __half g_ZTH[2][NXI * NXI], g_ZTL[2][NXI * NXI];
__device__ __half g_TtH[NXI * NXI], g_TtL[NXI * NXI];
__device__ __half g_RtH[768 * NXI], g_RtL[768 * NXI];

// ---------------- PTX helpers ----------------
__device__ __forceinline__ uint32_t smem_u32(const void* p) {
    uint32_t a;
    asm("{ .reg .u64 t; cvta.to.shared.u64 t, %1; cvt.u32.u64 %0, t; }" : "=r"(a) : "l"(p));
    return a;
}
#define LDSM4(r0, r1, r2, r3, addr) \
    asm volatile("ldmatrix.sync.aligned.m8n8.x4.shared.b16 {%0,%1,%2,%3}, [%4];" \
                 : "=r"(r0), "=r"(r1), "=r"(r2), "=r"(r3) : "r"(addr))
#define MMA16816(d, a, b0, b1) \
    asm volatile("mma.sync.aligned.m16n8k16.row.col.f32.f16.f16.f32 " \
                 "{%0,%1,%2,%3},{%4,%5,%6,%7},{%8,%9},{%0,%1,%2,%3};" \
                 : "+f"(d[0]), "+f"(d[1]), "+f"(d[2]), "+f"(d[3]) \
                 : "r"(a[0]), "r"(a[1]), "r"(a[2]), "r"(a[3]), "r"(b0), "r"(b1))
#define CPA16(smaddr, gptr) \
    asm volatile("cp.async.cg.shared.global [%0], [%1], 16;" :: "r"(smaddr), "l"(gptr))
#define CPCOMMIT() asm volatile("cp.async.commit_group;" ::: "memory")
#define CPWAIT1()  asm volatile("cp.async.wait_group 1;" ::: "memory")
#define CPWAIT0()  asm volatile("cp.async.wait_group 0;" ::: "memory")

__device__ __forceinline__ void split_store(__half* H, __half* L, size_t idx, float v) {
    __half h = __float2half(v);
    H[idx] = h;
    L[idx] = __float2half(v - __half2float(h));
}

// software grid barrier (all NBLK CTAs co-resident). Replay-safe.
__device__ __forceinline__ void gridbar(int nblk) {
    __threadfence();
    __syncthreads();
    if (threadIdx.x == 0) {
        unsigned e = ((volatile unsigned*)&g_barep)[0];
        unsigned t = atomicAdd(&g_barcnt, 1);
        if (t == (unsigned)nblk - 1) {
            g_barcnt = 0;
            __threadfence();
            atomicAdd(&g_barep, 1);
        } else {
            while (((volatile unsigned*)&g_barep)[0] == e) {}
        }
    }
    __syncthreads();
    __threadfence();
}

// ============ big batch GEMM (128x128 tiles, cp.async 3-stage, 1 sync/chunk) ============
// NPROD==2: hh + h_a*l_b. NPROD==1: hh only (pure fp16).
#define BK 32
#define LDSW (BK + 8)
template <int NPROD>
__global__ __launch_bounds__(256) void mma_gemm(
    const __half* __restrict__ Ah,
    const __half* __restrict__ Bh, const __half* __restrict__ Bl,
    int nchunks, int skip_at, int skip_amt, int lda, int ldb,
    float* __restrict__ out0, float* __restrict__ out1, int mode) {
    constexpr uint32_t SA_AH = 0u;
    constexpr uint32_t SA_BH = 10240u;
    constexpr uint32_t SA_BL = 20480u;                 // unused when NPROD==1
    constexpr uint32_t SBUFS = (NPROD == 2) ? 30720u : 20480u;
    extern __shared__ char dsm[];
    const uint32_t smb = smem_u32(dsm);
    const int tid = threadIdx.x;
    const int wid = tid >> 5, lane = tid & 31;
    const size_t m0 = (size_t)blockIdx.y * 128;
    const int n0 = blockIdx.x * 128;
    const int wm = (wid & 3) * 32;
    const int wn = (wid >> 2) * 64;

    float acc[2][8][4] = {};
    const int lr = tid >> 1;
    const int lc = (tid & 1) * 16;
    const int am = wm + (lane & 15);
    const int ak = (lane >> 4) * 8;
    const int bn = wn + (lane & 7) + (lane >> 4) * 8;
    const int bk = ((lane >> 3) & 1) * 8;

    auto issue = [&](int c) {
        const int kc = c * BK;
        const int col = (kc >= skip_at) ? kc + skip_amt : kc;
        const size_t oa = (m0 + lr) * (size_t)lda + col + lc;
        const size_t ob = (size_t)(n0 + lr) * ldb + col + lc;
        const uint32_t so = smb + (uint32_t)(c % 3) * SBUFS + (uint32_t)(lr * LDSW + lc) * 2;
        CPA16(so + SA_AH, Ah + oa); CPA16(so + SA_AH + 16, Ah + oa + 8);
        CPA16(so + SA_BH, Bh + ob); CPA16(so + SA_BH + 16, Bh + ob + 8);
        if (NPROD == 2) { CPA16(so + SA_BL, Bl + ob); CPA16(so + SA_BL + 16, Bl + ob + 8); }
        CPCOMMIT();
    };

    issue(0);
    if (nchunks > 1) issue(1);
    for (int c = 0; c < nchunks; ++c) {
        if (c + 1 < nchunks) { CPWAIT1(); } else { CPWAIT0(); }
        __syncthreads();
        if (c + 2 < nchunks) issue(c + 2);
        const uint32_t bb = smb + (uint32_t)(c % 3) * SBUFS;
#pragma unroll
        for (int k16 = 0; k16 < BK; k16 += 16) {
            uint32_t ahf[2][4], bhf[4][4], blf[4][4];
#pragma unroll
            for (int mi = 0; mi < 2; ++mi) {
                const uint32_t off = bb + (uint32_t)(((am + mi * 16) * LDSW + ak + k16) * 2);
                LDSM4(ahf[mi][0], ahf[mi][1], ahf[mi][2], ahf[mi][3], off + SA_AH);
            }
#pragma unroll
            for (int j = 0; j < 4; ++j) {
                const uint32_t off = bb + (uint32_t)(((bn + j * 16) * LDSW + bk + k16) * 2);
                LDSM4(bhf[j][0], bhf[j][1], bhf[j][2], bhf[j][3], off + SA_BH);
                if (NPROD == 2)
                    LDSM4(blf[j][0], blf[j][1], blf[j][2], blf[j][3], off + SA_BL);
            }
#pragma unroll
            for (int mi = 0; mi < 2; ++mi)
#pragma unroll
                for (int j = 0; j < 4; ++j)
#pragma unroll
                    for (int h = 0; h < 2; ++h) {
                        float* d = acc[mi][j * 2 + h];
                        MMA16816(d, ahf[mi], bhf[j][h * 2], bhf[j][h * 2 + 1]);
                        if (NPROD == 2)
                            MMA16816(d, ahf[mi], blf[j][h * 2], blf[j][h * 2 + 1]);
                    }
        }
    }
    const int rrow = lane >> 2;
    const int rcol = (lane & 3) * 2;
#pragma unroll
    for (int mi = 0; mi < 2; ++mi)
#pragma unroll
        for (int j = 0; j < 8; ++j) {
            const float* d = acc[mi][j];
            const int n = n0 + wn + j * 8 + rcol;
#pragma unroll
            for (int half = 0; half < 2; ++half) {
                const size_t m = m0 + wm + mi * 16 + rrow + half * 8;
                const float v0 = d[half * 2 + 0], v1 = d[half * 2 + 1];
                if (mode == 0) {
                    *(float2*)(out0 + m * 128 + n) = make_float2(v0, v1);
                } else {
                    if (n < NIN) *(float2*)(out0 + m * NIN + n) = make_float2(v0, v1);
                    else if (n < 576) *(float2*)(out1 + m * NXI + (n - NIN)) = make_float2(v0, v1);
                }
            }
        }
}

// ============ 64x64 GEMM core (fp16 3-product), logical tid + K offset ============
#define LDS2 (BK + 8)
__device__ __forceinline__ void gemm64_core(
    const __half* __restrict__ Ah, const __half* __restrict__ Al,
    const __half* __restrict__ Bh, const __half* __restrict__ Bl,
    int nchunks, int koff, int lda, int ldb, int m0, int n0,
    __half* sAh, __half* sAl, __half* sBh, __half* sBl,
    float acc[2][4][4], int t) {
    const int wid = t >> 5, lane = t & 31;
    const int wm = (wid & 1) * 32;
    const int wn = (wid >> 1) * 32;
    const int lr = t >> 1;
    const int lc = (t & 1) * 16;
    const uint32_t uAh = smem_u32(sAh), uAl = smem_u32(sAl);
    const uint32_t uBh = smem_u32(sBh), uBl = smem_u32(sBl);
    const int am = wm + (lane & 15);
    const int ak = (lane >> 4) * 8;
    const int bn = wn + (lane & 7) + (lane >> 4) * 8;
    const int bk = ((lane >> 3) & 1) * 8;

#pragma unroll
    for (int mi = 0; mi < 2; ++mi)
#pragma unroll
        for (int j = 0; j < 4; ++j)
#pragma unroll
            for (int q = 0; q < 4; ++q) acc[mi][j][q] = 0.0f;

    uint4 pa[2][2], pb[2][2];
    auto gload = [&](int c) {
        const int col = koff + c * BK;
        const size_t oa = (size_t)(m0 + lr) * lda + col + lc;
        const size_t ob = (size_t)(n0 + lr) * ldb + col + lc;
        pa[0][0] = *(const uint4*)(Ah + oa); pa[0][1] = *(const uint4*)(Ah + oa + 8);
        pa[1][0] = *(const uint4*)(Al + oa); pa[1][1] = *(const uint4*)(Al + oa + 8);
        pb[0][0] = *(const uint4*)(Bh + ob); pb[0][1] = *(const uint4*)(Bh + ob + 8);
        pb[1][0] = *(const uint4*)(Bl + ob); pb[1][1] = *(const uint4*)(Bl + ob + 8);
    };

    gload(0);
    for (int c = 0; c < nchunks; ++c) {
        const int so = lr * LDS2 + lc;
        *(uint4*)(sAh + so) = pa[0][0]; *(uint4*)(sAh + so + 8) = pa[0][1];
        *(uint4*)(sAl + so) = pa[1][0]; *(uint4*)(sAl + so + 8) = pa[1][1];
        *(uint4*)(sBh + so) = pb[0][0]; *(uint4*)(sBh + so + 8) = pb[0][1];
        *(uint4*)(sBl + so) = pb[1][0]; *(uint4*)(sBl + so + 8) = pb[1][1];
        __syncthreads();
        if (c + 1 < nchunks) gload(c + 1);
#pragma unroll
        for (int k16 = 0; k16 < BK; k16 += 16) {
            uint32_t ahf[2][4], alf[2][4], bhf[2][4], blf[2][4];
#pragma unroll
            for (int mi = 0; mi < 2; ++mi) {
                const uint32_t off = (uint32_t)(((am + mi * 16) * LDS2 + ak + k16) * 2);
                LDSM4(ahf[mi][0], ahf[mi][1], ahf[mi][2], ahf[mi][3], uAh + off);
                LDSM4(alf[mi][0], alf[mi][1], alf[mi][2], alf[mi][3], uAl + off);
            }
#pragma unroll
            for (int j = 0; j < 2; ++j) {
                const uint32_t off = (uint32_t)(((bn + j * 16) * LDS2 + bk + k16) * 2);
                LDSM4(bhf[j][0], bhf[j][1], bhf[j][2], bhf[j][3], uBh + off);
                LDSM4(blf[j][0], blf[j][1], blf[j][2], blf[j][3], uBl + off);
            }
#pragma unroll
            for (int mi = 0; mi < 2; ++mi)
#pragma unroll
                for (int j = 0; j < 2; ++j)
#pragma unroll
                    for (int h = 0; h < 2; ++h) {
                        float* d = acc[mi][j * 2 + h];
                        MMA16816(d, ahf[mi], bhf[j][h * 2], bhf[j][h * 2 + 1]);
                        MMA16816(d, ahf[mi], blf[j][h * 2], blf[j][h * 2 + 1]);
                        MMA16816(d, alf[mi], bhf[j][h * 2], bhf[j][h * 2 + 1]);
                    }
        }
        __syncthreads();
    }
}

// H GEMM over the 228 needed tiles only (1-D tile list)
__global__ __launch_bounds__(128) void tc2H(
    const __half* __restrict__ Ah, const __half* __restrict__ Al) {
    __shared__ __half sAh[64 * LDS2], sAl[64 * LDS2];
    __shared__ __half sBh[64 * LDS2], sBl[64 * LDS2];
    const int tid = threadIdx.x;
    const int wid = tid >> 5, lane = tid & 31;
    int b = blockIdx.x, m0, n0;
    if (b < 64)       { m0 = (b >> 3) * 64;          n0 = (b & 7) * 64; }           // H11
    else if (b < 84)  { int t = b - 64; m0 = 512 + (t / 10) * 64; n0 = (t % 10) * 64; } // H21|H22
    else              { int t = b - 84; m0 = 640 + (t / 18) * 64; n0 = (t % 18) * 64; } // bottom band
    const int wm = (wid & 1) * 32;
    const int wn = (wid >> 1) * 32;
    float acc[2][4][4];
    gemm64_core(Ah, Al, Ah, Al, HDIM / BK, 0, HDIM, HDIM, m0, n0, sAh, sAl, sBh, sBl, acc, tid);

    const int rrow = lane >> 2;
    const int rcol = (lane & 3) * 2;
#pragma unroll
    for (int mi = 0; mi < 2; ++mi)
#pragma unroll
        for (int j = 0; j < 4; ++j) {
            const float* d = acc[mi][j];
            const int n = n0 + wn + j * 8 + rcol;
#pragma unroll
            for (int half = 0; half < 2; ++half) {
                const int m = m0 + wm + mi * 16 + rrow + half * 8;
                float v0 = d[half * 2 + 0], v1 = d[half * 2 + 1];
                if (m == n) v0 += EPSV;
                if (m == n + 1) v1 += EPSV;
                *(float2*)(g_H + (size_t)m * HDIM + n) = make_float2(v0, v1);
            }
        }
}

// ============ fused persistent Newton (k-split 256-thr) + solve tail ============
#define NWT_BLOCKS 64
__global__ __launch_bounds__(256) void newton_fused() {
    __shared__ __half smt[8][64 * LDS2];       // 40 KB: 4 tile buffers per warpgroup
    const int tid = threadIdx.x;
    const int wg = tid >> 7;                   // warpgroup 0/1 = K halves
    const int wt = tid & 127;
    __half* bAh = smt[wg * 4 + 0];
    __half* bAl = smt[wg * 4 + 1];
    __half* bBh = smt[wg * 4 + 2];
    __half* bBl = smt[wg * 4 + 3];
    float* red = (float*)smt;                  // scratch reused after tiles drain
    const int m0 = (blockIdx.x >> 3) * 64;
    const int n0 = (blockIdx.x & 7) * 64;
    const int wid = wt >> 5, lane = wt & 31;
    const int wm = (wid & 1) * 32;
    const int wn = (wid >> 1) * 32;
    const int rrow = lane >> 2;
    const int rcol = (lane & 3) * 2;
    float acc[2][4][4];

    auto half_gemm = [&](const __half* Ah, const __half* Al,
                         const __half* Bh, const __half* Bl, int tm0, int tn0) {
        gemm64_core(Ah, Al, Bh, Bl, (NXI / BK) / 2, wg * (NXI / 2), NXI, NXI,
                    tm0, tn0, bAh, bAl, bBh, bBl, acc, wt);
        if (wg == 1) {
            float* dst = red + wt * 32;
#pragma unroll
            for (int mi = 0; mi < 2; ++mi)
#pragma unroll
                for (int j = 0; j < 4; ++j)
#pragma unroll
                    for (int q = 0; q < 4; ++q)
                        dst[(mi * 4 + j) * 4 + q] = acc[mi][j][q];
        }
        __syncthreads();
        if (wg == 0) {
            const float* src = red + wt * 32;
#pragma unroll
            for (int mi = 0; mi < 2; ++mi)
#pragma unroll
                for (int j = 0; j < 4; ++j)
#pragma unroll
                    for (int q = 0; q < 4; ++q)
                        acc[mi][j][q] += src[(mi * 4 + j) * 4 + q];
        }
        __syncthreads();
    };

    int cur = 0;
    for (int it = 0; it < NEWTON_ITERS; ++it) {
        half_gemm(g_MH, g_ML, g_ZTH[cur], g_ZTL[cur], m0, n0);
        if (wg == 0) {
#pragma unroll
            for (int mi = 0; mi < 2; ++mi)
#pragma unroll
                for (int j = 0; j < 4; ++j) {
                    const float* d = acc[mi][j];
                    const int n = n0 + wn + j * 8 + rcol;
#pragma unroll
                    for (int half = 0; half < 2; ++half) {
                        const int m = m0 + wm + mi * 16 + rrow + half * 8;
                        split_store(g_TtH, g_TtL, (size_t)n * NXI + m, d[half * 2 + 0]);
                        split_store(g_TtH, g_TtL, (size_t)(n + 1) * NXI + m, d[half * 2 + 1]);
                    }
                }
        }
        gridbar(NWT_BLOCKS);

        half_gemm(g_ZH[cur], g_ZL[cur], g_TtH, g_TtL, m0, n0);
        if (wg == 0) {
            const float* zin = g_Zf[cur];
            float* zout = g_Zf[cur ^ 1];
            const int nx = cur ^ 1;
#pragma unroll
            for (int mi = 0; mi < 2; ++mi)
#pragma unroll
                for (int j = 0; j < 4; ++j) {
                    const float* d = acc[mi][j];
                    const int n = n0 + wn + j * 8 + rcol;
#pragma unroll
                    for (int half = 0; half < 2; ++half) {
                        const int m = m0 + wm + mi * 16 + rrow + half * 8;
                        const size_t o = (size_t)m * NXI + n;
                        float v0 = 2.0f * zin[o] - d[half * 2 + 0];
                        float v1 = 2.0f * zin[o + 1] - d[half * 2 + 1];
                        *(float2*)(zout + o) = make_float2(v0, v1);
                        split_store(g_ZH[nx], g_ZL[nx], o, v0);
                        split_store(g_ZH[nx], g_ZL[nx], o + 1, v1);
                        split_store(g_ZTH[nx], g_ZTL[nx], (size_t)n * NXI + m, v0);
                        split_store(g_ZTH[nx], g_ZTL[nx], (size_t)(n + 1) * NXI + m, v1);
                    }
                }
        }
        gridbar(NWT_BLOCKS);
        cur ^= 1;
    }

    // solve tail: Wout[64+m, n] = sum_k Z[m,k] * Rt[n,k]
    const int fin = NEWTON_ITERS & 1;
    for (int t = blockIdx.x; t < 96; t += NWT_BLOCKS) {
        const int sm0 = (t & 7) * 64;
        const int sn0 = (t >> 3) * 64;
        half_gemm(g_ZH[fin], g_ZL[fin], g_RtH, g_RtL, sm0, sn0);
        if (wg == 0) {
#pragma unroll
            for (int mi = 0; mi < 2; ++mi)
#pragma unroll
                for (int j = 0; j < 4; ++j) {
                    const float* d = acc[mi][j];
                    const int n = sn0 + wn + j * 8 + rcol;
#pragma unroll
                    for (int half = 0; half < 2; ++half) {
                        const int m = sm0 + wm + mi * 16 + rrow + half * 8;
                        const size_t o = (size_t)(64 + m) * 768 + n;
                        split_store(g_WoutH, g_WoutL, o, d[half * 2 + 0]);
                        split_store(g_WoutH, g_WoutL, o + 1, d[half * 2 + 1]);
                    }
                }
        }
    }
}

// ---------------- builders ----------------
__global__ void conv_Xt(const float* __restrict__ X) {
    __shared__ float t[32][33];
    const int bx = blockIdx.x * 32, by = blockIdx.y * 32;
    const int tx = threadIdx.x, ty = threadIdx.y;
#pragma unroll
    for (int r = 0; r < 32; r += 8)
        t[ty + r][tx] = X[(size_t)(by + ty + r) * HDIM + bx + tx];
    __syncthreads();
#pragma unroll
    for (int r = 0; r < 32; r += 8) {
        const float v = t[tx][ty + r];
        split_store(g_XtH, g_XtL, (size_t)(bx + ty + r) * HDIM + by + tx, v);
    }
}
__global__ void build_WpreSplit(const float* __restrict__ D12) {
    int idx = blockIdx.x * blockDim.x + threadIdx.x;
    if (idx >= LDIM * 640) return;
    int rr = idx / 640, c = idx - rr * 640;
    float v = (c < NXI) ? -g_H[(size_t)(NXI + rr) * HDIM + c] : D12[rr * NSTATES + (c - NXI)];
    int dc = (c < NXI) ? c : c + 128;
    split_store(g_WpreH, g_WpreL, (size_t)rr * 768 + dc, v);
}
__global__ void build_D11() {
    int idx = blockIdx.x * blockDim.x + threadIdx.x;
    if (idx >= LDIM * LDIM) return;
    int i = idx >> 7, j = idx & 127;
    g_D11[idx] = (j < i) ? -g_H[(size_t)(NXI + i) * HDIM + NXI + j] : 0.0f;
    if (j == i) g_LamInv[i] = 2.0f / g_H[(size_t)(NXI + i) * HDIM + NXI + i];
}
// merged: MZ (0..262143), Rt (..655359), WoutTop (..704511)
__global__ void build_all(const float* __restrict__ Y, const float* __restrict__ B2,
                          const float* __restrict__ C2, const float* __restrict__ D21,
                          const float* __restrict__ D22) {
    int idx = blockIdx.x * blockDim.x + threadIdx.x;
    if (idx < NXI * NXI) {
        int i = idx >> 9, j = idx & 511;
        float dinv = 2.0f / (g_H[(size_t)i * HDIM + i] + g_H[(size_t)(640 + i) * HDIM + 640 + i]);
        float e = 0.5f * (g_H[(size_t)i * HDIM + j] + g_H[(size_t)(640 + i) * HDIM + 640 + j] +
                          Y[(size_t)i * NXI + j] - Y[(size_t)j * NXI + i]);
        float m = dinv * e;
        split_store(g_MH, g_ML, idx, m);
        float z = ((i == j) ? 2.0f * ALPHA : 0.0f) - ALPHA * ALPHA * m;
        g_Zf[0][idx] = z;
        split_store(g_ZH[0], g_ZL[0], idx, z);
        split_store(g_ZTH[0], g_ZTL[0], (size_t)j * NXI + i, z);
    } else if (idx < NXI * NXI + NXI * 768) {
        int t = idx - NXI * NXI;
        int i = t / 768, c = t - i * 768;
        float dinv = 2.0f / (g_H[(size_t)i * HDIM + i] + g_H[(size_t)(640 + i) * HDIM + 640 + i]);
        float v = (c < 640) ? g_H[(size_t)(640 + i) * HDIM + c] : B2[i * NSTATES + (c - 640)];
        split_store(g_RtH, g_RtL, (size_t)c * NXI + i, dinv * v);
    } else if (idx < NXI * NXI + NXI * 768 + NIN * 768) {
        int t = idx - NXI * NXI - NXI * 768;
        int rr = t / 768, c = t - rr * 768;
        float v = (c < NXI) ? C2[rr * NXI + c]
                            : (c < 640 ? D21[rr * LDIM + (c - NXI)] : D22[rr * NSTATES + (c - 640)]);
        split_store(g_WoutH, g_WoutL, t, v);
    }
}
__global__ void conv_A(const float* __restrict__ xi, const float* __restrict__ w) {
    size_t idx = (size_t)blockIdx.x * blockDim.x + threadIdx.x;
    size_t b = idx / 160;
    int c0 = (int)(idx - b * 160) * 4;
    if (b >= BATCHN) return;
    float4 v;
    int dc;
    if (c0 < NXI) { v = *(const float4*)(xi + b * NXI + c0); dc = c0; }
    else          { v = *(const float4*)(w + b * NSTATES + (c0 - NXI)); dc = c0 + 128; }
    size_t o = b * 768 + dc;
    split_store(g_AH, g_AL, o + 0, v.x);
    split_store(g_AH, g_AL, o + 1, v.y);
    split_store(g_AH, g_AL, o + 2, v.z);
    split_store(g_AH, g_AL, o + 3, v.w);
}

// ---------------- tanh forward-substitution scan (coalesced split stores) ----------------
__global__ __launch_bounds__(64) void eps_kernel() {
    __shared__ float es[128 * 65];
    __shared__ float li[128];
    int tid = threadIdx.x;
    size_t b = (size_t)blockIdx.x * 64 + tid;
    for (int i = tid; i < 128; i += 64) li[i] = g_LamInv[i];
    __syncthreads();
    for (int i = 0; i < 128; ++i) {
        float v = g_pre[b * 128 + i];
        const float* __restrict__ dr = &g_D11[i * 128];
        float v0 = 0.f, v1 = 0.f, v2 = 0.f, v3 = 0.f;
        int j = 0;
        for (; j + 3 < i; j += 4) {
            v0 = fmaf(es[(j + 0) * 65 + tid], dr[j + 0], v0);
            v1 = fmaf(es[(j + 1) * 65 + tid], dr[j + 1], v1);
            v2 = fmaf(es[(j + 2) * 65 + tid], dr[j + 2], v2);
            v3 = fmaf(es[(j + 3) * 65 + tid], dr[j + 3], v3);
        }
        for (; j < i; ++j) v0 = fmaf(es[j * 65 + tid], dr[j], v0);
        v += (v0 + v1) + (v2 + v3);
        es[i * 65 + tid] = tanhf(v * li[i]);
    }
    __syncthreads();
    const size_t b0 = (size_t)blockIdx.x * 64;
    for (int r = 0; r < 64; ++r) {
        const size_t o = (b0 + r) * 768 + 512;
        split_store(g_AH, g_AL, o + tid, es[tid * 65 + r]);
        split_store(g_AH, g_AL, o + 64 + tid, es[(64 + tid) * 65 + r]);
    }
}

// ---------------- launch ----------------
extern "C" void kernel_launch(void* const* d_in, const int* in_sizes, int n_in,
                              void* d_out, int out_size) {
    (void)in_sizes; (void)n_in; (void)out_size;
    const float* w   = (const float*)d_in[1];
    const float* xi  = (const float*)d_in[2];
    const float* X   = (const float*)d_in[3];
    const float* Y   = (const float*)d_in[4];
    const float* B2  = (const float*)d_in[5];
    const float* C2  = (const float*)d_in[6];
    const float* D21 = (const float*)d_in[7];
    const float* D22 = (const float*)d_in[8];
    const float* D12 = (const float*)d_in[9];
    float* out   = (float*)d_out;
    float* out_u = out;
    float* out_x = out + (size_t)BATCHN * NIN;

    static cudaStream_t s2;
    static cudaEvent_t evStart, evH, evJoin;
    static bool inited = false;
    if (!inited) {
        cudaStreamCreateWithFlags(&s2, cudaStreamNonBlocking);
        cudaEventCreateWithFlags(&evStart, cudaEventDisableTiming);
        cudaEventCreateWithFlags(&evH, cudaEventDisableTiming);
        cudaEventCreateWithFlags(&evJoin, cudaEventDisableTiming);
        cudaFuncSetAttribute(mma_gemm<2>, cudaFuncAttributeMaxDynamicSharedMemorySize, 3 * 30720);
        cudaFuncSetAttribute(mma_gemm<1>, cudaFuncAttributeMaxDynamicSharedMemorySize, 3 * 20480);
        inited = true;
    }

    float* pPre;
    __half *pAH, *pWpreH, *pWpreL, *pWoutH, *pWoutL, *pXtH, *pXtL;
    cudaGetSymbolAddress((void**)&pPre, g_pre);
    cudaGetSymbolAddress((void**)&pAH, g_AH);
    cudaGetSymbolAddress((void**)&pWpreH, g_WpreH);
    cudaGetSymbolAddress((void**)&pWpreL, g_WpreL);
    cudaGetSymbolAddress((void**)&pWoutH, g_WoutH);
    cudaGetSymbolAddress((void**)&pWoutL, g_WoutL);
    cudaGetSymbolAddress((void**)&pXtH, g_XtH);
    cudaGetSymbolAddress((void**)&pXtL, g_XtL);

    // ---- top fork: conv_A on s2 in parallel with Xt/H on s0 ----
    cudaEventRecord(evStart, 0);
    cudaStreamWaitEvent(s2, evStart, 0);
    conv_A<<<(BATCHN * 160 + 255) / 256, 256, 0, s2>>>(xi, w);

    conv_Xt<<<dim3(HDIM / 32, HDIM / 32), dim3(32, 8)>>>(X);
    tc2H<<<228, 128>>>(pXtH, pXtL);
    cudaEventRecord(evH, 0);
    cudaStreamWaitEvent(s2, evH, 0);

    // ---- branch A (s2): Wpre/D11 from H -> pre-GEMM (2-product) -> eps ----
    build_WpreSplit<<<(LDIM * 640 + 255) / 256, 256, 0, s2>>>(D12);
    build_D11<<<(LDIM * LDIM + 255) / 256, 256, 0, s2>>>();
    mma_gemm<2><<<dim3(1, BATCHN / 128), 256, 3 * 30720, s2>>>(
        pAH, pWpreH, pWpreL, 20, 512, 128, 768, 768, pPre, nullptr, 0);
    eps_kernel<<<BATCHN / 64, 64, 0, s2>>>();
    cudaEventRecord(evJoin, s2);

    // ---- branch B (s0): merged builders -> fused Newton (k-split) + solve tail ----
    build_all<<<(704512 + 255) / 256, 256>>>(Y, B2, C2, D21, D22);
    newton_fused<<<NWT_BLOCKS, 256>>>();

    // ---- join ----
    cudaStreamWaitEvent(0, evJoin, 0);

    // [u | xi_] = [xi|eps|w] @ Wout^T  (single fp16 product)
    mma_gemm<1><<<dim3(5, BATCHN / 128), 256, 3 * 20480>>>(
        pAH, pWoutH, pWoutL, 24, 1 << 30, 0, 768, 768, out_u, out_x, 1);
}

// round 16
// speedup vs baseline: 1.6651x; 1.0976x over previous
#include <cuda_runtime.h>
#include <cuda_fp16.h>
#include <math.h>
#include <stdint.h>

#define NXI 512
#define LDIM 128
#define NSTATES 128
#define NIN 64
#define HDIM 1152           // 2*NXI + LDIM
#define BATCHN 32768
#define EPSV 0.001f
#define ALPHA 0.55f
#define NEWTON_ITERS 7      // + fused first step = 8 squarings

// ---------------- device scratch ----------------
__device__ float g_H[HDIM * HDIM];
__device__ float g_Zf[2][NXI * NXI];
__device__ float g_D11[LDIM * LDIM];
__device__ float g_LamInv[LDIM];
__device__ float g_pre[(size_t)BATCHN * LDIM];
__device__ unsigned g_barcnt, g_barep;     // software grid barrier state (zero-init)

// fp16 operand arrays (hi-only where the consumer is 1-product)
__device__ __half g_AH[(size_t)BATCHN * 768];   // [xi | eps | w]
__device__ __half g_WpreH[LDIM * 768];
__device__ __half g_WoutH[640 * 768];           // rows 576..639 stay zero
__device__ __half g_XtH[HDIM * HDIM];
__device__ __half g_XtL[HDIM * HDIM];
__device__ __half g_MH[NXI * NXI], g_ML[NXI * NXI];
__device__ __half g_ZH[2][NXI * NXI], g_ZL[2][NXI * NXI];
__device__ __half g_ZTH[2][NXI * NXI], g_ZTL[2][NXI * NXI];
__device__ __half g_TtH[NXI * NXI], g_TtL[NXI * NXI];
__device__ __half g_RtH[768 * NXI], g_RtL[768 * NXI];

// ---------------- PTX helpers ----------------
__device__ __forceinline__ uint32_t smem_u32(const void* p) {
    uint32_t a;
    asm("{ .reg .u64 t; cvta.to.shared.u64 t, %1; cvt.u32.u64 %0, t; }" : "=r"(a) : "l"(p));
    return a;
}
#define LDSM4(r0, r1, r2, r3, addr) \
    asm volatile("ldmatrix.sync.aligned.m8n8.x4.shared.b16 {%0,%1,%2,%3}, [%4];" \
                 : "=r"(r0), "=r"(r1), "=r"(r2), "=r"(r3) : "r"(addr))
#define MMA16816(d, a, b0, b1) \
    asm volatile("mma.sync.aligned.m16n8k16.row.col.f32.f16.f16.f32 " \
                 "{%0,%1,%2,%3},{%4,%5,%6,%7},{%8,%9},{%0,%1,%2,%3};" \
                 : "+f"(d[0]), "+f"(d[1]), "+f"(d[2]), "+f"(d[3]) \
                 : "r"(a[0]), "r"(a[1]), "r"(a[2]), "r"(a[3]), "r"(b0), "r"(b1))
#define CPA16(smaddr, gptr) \
    asm volatile("cp.async.cg.shared.global [%0], [%1], 16;" :: "r"(smaddr), "l"(gptr))
#define CPCOMMIT() asm volatile("cp.async.commit_group;" ::: "memory")
#define CPWAIT1()  asm volatile("cp.async.wait_group 1;" ::: "memory")
#define CPWAIT0()  asm volatile("cp.async.wait_group 0;" ::: "memory")

__device__ __forceinline__ void split_store(__half* H, __half* L, size_t idx, float v) {
    __half h = __float2half(v);
    H[idx] = h;
    L[idx] = __float2half(v - __half2float(h));
}

// software grid barrier (all NBLK CTAs co-resident). Replay-safe.
__device__ __forceinline__ void gridbar(int nblk) {
    __threadfence();
    __syncthreads();
    if (threadIdx.x == 0) {
        unsigned e = ((volatile unsigned*)&g_barep)[0];
        unsigned t = atomicAdd(&g_barcnt, 1);
        if (t == (unsigned)nblk - 1) {
            g_barcnt = 0;
            __threadfence();
            atomicAdd(&g_barep, 1);
        } else {
            while (((volatile unsigned*)&g_barep)[0] == e) {}
        }
    }
    __syncthreads();
    __threadfence();
}

// ============ big batch GEMM (128x128 tiles, pure fp16, cp.async 3-stage) ============
#define BK 32
#define LDSW (BK + 8)
#define SA_AH 0u
#define SA_BH 10240u
#define SBUFS 20480u
__global__ __launch_bounds__(256) void mma_gemm(
    const __half* __restrict__ Ah, const __half* __restrict__ Bh,
    int nchunks, int skip_at, int skip_amt, int lda, int ldb,
    float* __restrict__ out0, float* __restrict__ out1, int mode) {
    extern __shared__ char dsm[];
    const uint32_t smb = smem_u32(dsm);
    const int tid = threadIdx.x;
    const int wid = tid >> 5, lane = tid & 31;
    const size_t m0 = (size_t)blockIdx.y * 128;
    const int n0 = blockIdx.x * 128;
    const int wm = (wid & 3) * 32;
    const int wn = (wid >> 2) * 64;

    float acc[2][8][4] = {};
    const int lr = tid >> 1;
    const int lc = (tid & 1) * 16;
    const int am = wm + (lane & 15);
    const int ak = (lane >> 4) * 8;
    const int bn = wn + (lane & 7) + (lane >> 4) * 8;
    const int bk = ((lane >> 3) & 1) * 8;

    auto issue = [&](int c) {
        const int kc = c * BK;
        const int col = (kc >= skip_at) ? kc + skip_amt : kc;
        const size_t oa = (m0 + lr) * (size_t)lda + col + lc;
        const size_t ob = (size_t)(n0 + lr) * ldb + col + lc;
        const uint32_t so = smb + (uint32_t)(c % 3) * SBUFS + (uint32_t)(lr * LDSW + lc) * 2;
        CPA16(so + SA_AH, Ah + oa); CPA16(so + SA_AH + 16, Ah + oa + 8);
        CPA16(so + SA_BH, Bh + ob); CPA16(so + SA_BH + 16, Bh + ob + 8);
        CPCOMMIT();
    };

    issue(0);
    if (nchunks > 1) issue(1);
    for (int c = 0; c < nchunks; ++c) {
        if (c + 1 < nchunks) { CPWAIT1(); } else { CPWAIT0(); }
        __syncthreads();
        if (c + 2 < nchunks) issue(c + 2);
        const uint32_t bb = smb + (uint32_t)(c % 3) * SBUFS;
#pragma unroll
        for (int k16 = 0; k16 < BK; k16 += 16) {
            uint32_t ahf[2][4], bhf[4][4];
#pragma unroll
            for (int mi = 0; mi < 2; ++mi) {
                const uint32_t off = bb + (uint32_t)(((am + mi * 16) * LDSW + ak + k16) * 2);
                LDSM4(ahf[mi][0], ahf[mi][1], ahf[mi][2], ahf[mi][3], off + SA_AH);
            }
#pragma unroll
            for (int j = 0; j < 4; ++j) {
                const uint32_t off = bb + (uint32_t)(((bn + j * 16) * LDSW + bk + k16) * 2);
                LDSM4(bhf[j][0], bhf[j][1], bhf[j][2], bhf[j][3], off + SA_BH);
            }
#pragma unroll
            for (int mi = 0; mi < 2; ++mi)
#pragma unroll
                for (int j = 0; j < 4; ++j)
#pragma unroll
                    for (int h = 0; h < 2; ++h)
                        MMA16816(acc[mi][j * 2 + h], ahf[mi], bhf[j][h * 2], bhf[j][h * 2 + 1]);
        }
    }
    const int rrow = lane >> 2;
    const int rcol = (lane & 3) * 2;
#pragma unroll
    for (int mi = 0; mi < 2; ++mi)
#pragma unroll
        for (int j = 0; j < 8; ++j) {
            const float* d = acc[mi][j];
            const int n = n0 + wn + j * 8 + rcol;
#pragma unroll
            for (int half = 0; half < 2; ++half) {
                const size_t m = m0 + wm + mi * 16 + rrow + half * 8;
                const float v0 = d[half * 2 + 0], v1 = d[half * 2 + 1];
                if (mode == 0) {
                    *(float2*)(out0 + m * 128 + n) = make_float2(v0, v1);
                } else {
                    if (n < NIN) *(float2*)(out0 + m * NIN + n) = make_float2(v0, v1);
                    else if (n < 576) *(float2*)(out1 + m * NXI + (n - NIN)) = make_float2(v0, v1);
                }
            }
        }
}

// ============ 64x64 GEMM core (fp16 3-product), logical tid + K offset ============
#define LDS2 (BK + 8)
__device__ __forceinline__ void gemm64_core(
    const __half* __restrict__ Ah, const __half* __restrict__ Al,
    const __half* __restrict__ Bh, const __half* __restrict__ Bl,
    int nchunks, int koff, int lda, int ldb, int m0, int n0,
    __half* sAh, __half* sAl, __half* sBh, __half* sBl,
    float acc[2][4][4], int t) {
    const int wid = t >> 5, lane = t & 31;
    const int wm = (wid & 1) * 32;
    const int wn = (wid >> 1) * 32;
    const int lr = t >> 1;
    const int lc = (t & 1) * 16;
    const uint32_t uAh = smem_u32(sAh), uAl = smem_u32(sAl);
    const uint32_t uBh = smem_u32(sBh), uBl = smem_u32(sBl);
    const int am = wm + (lane & 15);
    const int ak = (lane >> 4) * 8;
    const int bn = wn + (lane & 7) + (lane >> 4) * 8;
    const int bk = ((lane >> 3) & 1) * 8;

#pragma unroll
    for (int mi = 0; mi < 2; ++mi)
#pragma unroll
        for (int j = 0; j < 4; ++j)
#pragma unroll
            for (int q = 0; q < 4; ++q) acc[mi][j][q] = 0.0f;

    uint4 pa[2][2], pb[2][2];
    auto gload = [&](int c) {
        const int col = koff + c * BK;
        const size_t oa = (size_t)(m0 + lr) * lda + col + lc;
        const size_t ob = (size_t)(n0 + lr) * ldb + col + lc;
        pa[0][0] = *(const uint4*)(Ah + oa); pa[0][1] = *(const uint4*)(Ah + oa + 8);
        pa[1][0] = *(const uint4*)(Al + oa); pa[1][1] = *(const uint4*)(Al + oa + 8);
        pb[0][0] = *(const uint4*)(Bh + ob); pb[0][1] = *(const uint4*)(Bh + ob + 8);
        pb[1][0] = *(const uint4*)(Bl + ob); pb[1][1] = *(const uint4*)(Bl + ob + 8);
    };

    gload(0);
    for (int c = 0; c < nchunks; ++c) {
        const int so = lr * LDS2 + lc;
        *(uint4*)(sAh + so) = pa[0][0]; *(uint4*)(sAh + so + 8) = pa[0][1];
        *(uint4*)(sAl + so) = pa[1][0]; *(uint4*)(sAl + so + 8) = pa[1][1];
        *(uint4*)(sBh + so) = pb[0][0]; *(uint4*)(sBh + so + 8) = pb[0][1];
        *(uint4*)(sBl + so) = pb[1][0]; *(uint4*)(sBl + so + 8) = pb[1][1];
        __syncthreads();
        if (c + 1 < nchunks) gload(c + 1);
#pragma unroll
        for (int k16 = 0; k16 < BK; k16 += 16) {
            uint32_t ahf[2][4], alf[2][4], bhf[2][4], blf[2][4];
#pragma unroll
            for (int mi = 0; mi < 2; ++mi) {
                const uint32_t off = (uint32_t)(((am + mi * 16) * LDS2 + ak + k16) * 2);
                LDSM4(ahf[mi][0], ahf[mi][1], ahf[mi][2], ahf[mi][3], uAh + off);
                LDSM4(alf[mi][0], alf[mi][1], alf[mi][2], alf[mi][3], uAl + off);
            }
#pragma unroll
            for (int j = 0; j < 2; ++j) {
                const uint32_t off = (uint32_t)(((bn + j * 16) * LDS2 + bk + k16) * 2);
                LDSM4(bhf[j][0], bhf[j][1], bhf[j][2], bhf[j][3], uBh + off);
                LDSM4(blf[j][0], blf[j][1], blf[j][2], blf[j][3], uBl + off);
            }
#pragma unroll
            for (int mi = 0; mi < 2; ++mi)
#pragma unroll
                for (int j = 0; j < 2; ++j)
#pragma unroll
                    for (int h = 0; h < 2; ++h) {
                        float* d = acc[mi][j * 2 + h];
                        MMA16816(d, ahf[mi], bhf[j][h * 2], bhf[j][h * 2 + 1]);
                        MMA16816(d, ahf[mi], blf[j][h * 2], blf[j][h * 2 + 1]);
                        MMA16816(d, alf[mi], bhf[j][h * 2], bhf[j][h * 2 + 1]);
                    }
        }
        __syncthreads();
    }
}

// H GEMM over the 228 needed tiles only (1-D tile list)
__global__ __launch_bounds__(128) void tc2H(
    const __half* __restrict__ Ah, const __half* __restrict__ Al) {
    __shared__ __half sAh[64 * LDS2], sAl[64 * LDS2];
    __shared__ __half sBh[64 * LDS2], sBl[64 * LDS2];
    const int tid = threadIdx.x;
    const int wid = tid >> 5, lane = tid & 31;
    int b = blockIdx.x, m0, n0;
    if (b < 64)       { m0 = (b >> 3) * 64;          n0 = (b & 7) * 64; }
    else if (b < 84)  { int t = b - 64; m0 = 512 + (t / 10) * 64; n0 = (t % 10) * 64; }
    else              { int t = b - 84; m0 = 640 + (t / 18) * 64; n0 = (t % 18) * 64; }
    const int wm = (wid & 1) * 32;
    const int wn = (wid >> 1) * 32;
    float acc[2][4][4];
    gemm64_core(Ah, Al, Ah, Al, HDIM / BK, 0, HDIM, HDIM, m0, n0, sAh, sAl, sBh, sBl, acc, tid);

    const int rrow = lane >> 2;
    const int rcol = (lane & 3) * 2;
#pragma unroll
    for (int mi = 0; mi < 2; ++mi)
#pragma unroll
        for (int j = 0; j < 4; ++j) {
            const float* d = acc[mi][j];
            const int n = n0 + wn + j * 8 + rcol;
#pragma unroll
            for (int half = 0; half < 2; ++half) {
                const int m = m0 + wm + mi * 16 + rrow + half * 8;
                float v0 = d[half * 2 + 0], v1 = d[half * 2 + 1];
                if (m == n) v0 += EPSV;
                if (m == n + 1) v1 += EPSV;
                *(float2*)(g_H + (size_t)m * HDIM + n) = make_float2(v0, v1);
            }
        }
}

// ============ fused persistent Newton (k-split 256-thr) + solve tail ============
#define NWT_BLOCKS 64
__global__ __launch_bounds__(256) void newton_fused() {
    __shared__ __half smt[8][64 * LDS2];
    const int tid = threadIdx.x;
    const int wg = tid >> 7;
    const int wt = tid & 127;
    __half* bAh = smt[wg * 4 + 0];
    __half* bAl = smt[wg * 4 + 1];
    __half* bBh = smt[wg * 4 + 2];
    __half* bBl = smt[wg * 4 + 3];
    float* red = (float*)smt;
    const int m0 = (blockIdx.x >> 3) * 64;
    const int n0 = (blockIdx.x & 7) * 64;
    const int wid = wt >> 5, lane = wt & 31;
    const int wm = (wid & 1) * 32;
    const int wn = (wid >> 1) * 32;
    const int rrow = lane >> 2;
    const int rcol = (lane & 3) * 2;
    float acc[2][4][4];

    auto half_gemm = [&](const __half* Ah, const __half* Al,
                         const __half* Bh, const __half* Bl, int tm0, int tn0) {
        gemm64_core(Ah, Al, Bh, Bl, (NXI / BK) / 2, wg * (NXI / 2), NXI, NXI,
                    tm0, tn0, bAh, bAl, bBh, bBl, acc, wt);
        if (wg == 1) {
            float* dst = red + wt * 32;
#pragma unroll
            for (int mi = 0; mi < 2; ++mi)
#pragma unroll
                for (int j = 0; j < 4; ++j)
#pragma unroll
                    for (int q = 0; q < 4; ++q)
                        dst[(mi * 4 + j) * 4 + q] = acc[mi][j][q];
        }
        __syncthreads();
        if (wg == 0) {
            const float* src = red + wt * 32;
#pragma unroll
            for (int mi = 0; mi < 2; ++mi)
#pragma unroll
                for (int j = 0; j < 4; ++j)
#pragma unroll
                    for (int q = 0; q < 4; ++q)
                        acc[mi][j][q] += src[(mi * 4 + j) * 4 + q];
        }
        __syncthreads();
    };

    int cur = 0;
    for (int it = 0; it < NEWTON_ITERS; ++it) {
        half_gemm(g_MH, g_ML, g_ZTH[cur], g_ZTL[cur], m0, n0);
        if (wg == 0) {
#pragma unroll
            for (int mi = 0; mi < 2; ++mi)
#pragma unroll
                for (int j = 0; j < 4; ++j) {
                    const float* d = acc[mi][j];
                    const int n = n0 + wn + j * 8 + rcol;
#pragma unroll
                    for (int half = 0; half < 2; ++half) {
                        const int m = m0 + wm + mi * 16 + rrow + half * 8;
                        split_store(g_TtH, g_TtL, (size_t)n * NXI + m, d[half * 2 + 0]);
                        split_store(g_TtH, g_TtL, (size_t)(n + 1) * NXI + m, d[half * 2 + 1]);
                    }
                }
        }
        gridbar(NWT_BLOCKS);

        half_gemm(g_ZH[cur], g_ZL[cur], g_TtH, g_TtL, m0, n0);
        if (wg == 0) {
            const float* zin = g_Zf[cur];
            float* zout = g_Zf[cur ^ 1];
            const int nx = cur ^ 1;
#pragma unroll
            for (int mi = 0; mi < 2; ++mi)
#pragma unroll
                for (int j = 0; j < 4; ++j) {
                    const float* d = acc[mi][j];
                    const int n = n0 + wn + j * 8 + rcol;
#pragma unroll
                    for (int half = 0; half < 2; ++half) {
                        const int m = m0 + wm + mi * 16 + rrow + half * 8;
                        const size_t o = (size_t)m * NXI + n;
                        float v0 = 2.0f * zin[o] - d[half * 2 + 0];
                        float v1 = 2.0f * zin[o + 1] - d[half * 2 + 1];
                        *(float2*)(zout + o) = make_float2(v0, v1);
                        split_store(g_ZH[nx], g_ZL[nx], o, v0);
                        split_store(g_ZH[nx], g_ZL[nx], o + 1, v1);
                        split_store(g_ZTH[nx], g_ZTL[nx], (size_t)n * NXI + m, v0);
                        split_store(g_ZTH[nx], g_ZTL[nx], (size_t)(n + 1) * NXI + m, v1);
                    }
                }
        }
        gridbar(NWT_BLOCKS);
        cur ^= 1;
    }

    // solve tail: Wout[64+m, n] = sum_k Z[m,k] * Rt[n,k]  (hi-only output)
    const int fin = NEWTON_ITERS & 1;
    for (int t = blockIdx.x; t < 96; t += NWT_BLOCKS) {
        const int sm0 = (t & 7) * 64;
        const int sn0 = (t >> 3) * 64;
        half_gemm(g_ZH[fin], g_ZL[fin], g_RtH, g_RtL, sm0, sn0);
        if (wg == 0) {
#pragma unroll
            for (int mi = 0; mi < 2; ++mi)
#pragma unroll
                for (int j = 0; j < 4; ++j) {
                    const float* d = acc[mi][j];
                    const int n = sn0 + wn + j * 8 + rcol;
#pragma unroll
                    for (int half = 0; half < 2; ++half) {
                        const int m = sm0 + wm + mi * 16 + rrow + half * 8;
                        const size_t o = (size_t)(64 + m) * 768 + n;
                        g_WoutH[o] = __float2half(d[half * 2 + 0]);
                        g_WoutH[o + 1] = __float2half(d[half * 2 + 1]);
                    }
                }
        }
    }
}

// ---------------- builders ----------------
__global__ void conv_Xt(const float* __restrict__ X) {
    __shared__ float t[32][33];
    const int bx = blockIdx.x * 32, by = blockIdx.y * 32;
    const int tx = threadIdx.x, ty = threadIdx.y;
#pragma unroll
    for (int r = 0; r < 32; r += 8)
        t[ty + r][tx] = X[(size_t)(by + ty + r) * HDIM + bx + tx];
    __syncthreads();
#pragma unroll
    for (int r = 0; r < 32; r += 8) {
        const float v = t[tx][ty + r];
        split_store(g_XtH, g_XtL, (size_t)(bx + ty + r) * HDIM + by + tx, v);
    }
}
// merged: Wpre (hi-only; cols 0..511 = -H21, 640..767 = D12) + D11/LamInv
__global__ void build_WD(const float* __restrict__ D12) {
    int idx = blockIdx.x * blockDim.x + threadIdx.x;
    if (idx < LDIM * 640) {
        int rr = idx / 640, c = idx - rr * 640;
        float v = (c < NXI) ? -g_H[(size_t)(NXI + rr) * HDIM + c] : D12[rr * NSTATES + (c - NXI)];
        int dc = (c < NXI) ? c : c + 128;
        g_WpreH[(size_t)rr * 768 + dc] = __float2half(v);
    } else if (idx < LDIM * 640 + LDIM * LDIM) {
        int t = idx - LDIM * 640;
        int i = t >> 7, j = t & 127;
        g_D11[t] = (j < i) ? -g_H[(size_t)(NXI + i) * HDIM + NXI + j] : 0.0f;
        if (j == i) g_LamInv[i] = 2.0f / g_H[(size_t)(NXI + i) * HDIM + NXI + i];
    }
}
// merged: MZ, Rt, WoutTop (hi-only Wout)
__global__ void build_all(const float* __restrict__ Y, const float* __restrict__ B2,
                          const float* __restrict__ C2, const float* __restrict__ D21,
                          const float* __restrict__ D22) {
    int idx = blockIdx.x * blockDim.x + threadIdx.x;
    if (idx < NXI * NXI) {
        int i = idx >> 9, j = idx & 511;
        float dinv = 2.0f / (g_H[(size_t)i * HDIM + i] + g_H[(size_t)(640 + i) * HDIM + 640 + i]);
        float e = 0.5f * (g_H[(size_t)i * HDIM + j] + g_H[(size_t)(640 + i) * HDIM + 640 + j] +
                          Y[(size_t)i * NXI + j] - Y[(size_t)j * NXI + i]);
        float m = dinv * e;
        split_store(g_MH, g_ML, idx, m);
        float z = ((i == j) ? 2.0f * ALPHA : 0.0f) - ALPHA * ALPHA * m;
        g_Zf[0][idx] = z;
        split_store(g_ZH[0], g_ZL[0], idx, z);
        split_store(g_ZTH[0], g_ZTL[0], (size_t)j * NXI + i, z);
    } else if (idx < NXI * NXI + NXI * 768) {
        int t = idx - NXI * NXI;
        int i = t / 768, c = t - i * 768;
        float dinv = 2.0f / (g_H[(size_t)i * HDIM + i] + g_H[(size_t)(640 + i) * HDIM + 640 + i]);
        float v = (c < 640) ? g_H[(size_t)(640 + i) * HDIM + c] : B2[i * NSTATES + (c - 640)];
        split_store(g_RtH, g_RtL, (size_t)c * NXI + i, dinv * v);
    } else if (idx < NXI * NXI + NXI * 768 + NIN * 768) {
        int t = idx - NXI * NXI - NXI * 768;
        int rr = t / 768, c = t - rr * 768;
        float v = (c < NXI) ? C2[rr * NXI + c]
                            : (c < 640 ? D21[rr * LDIM + (c - NXI)] : D22[rr * NSTATES + (c - 640)]);
        g_WoutH[t] = __float2half(v);
    }
}
// A conversion: hi-only
__global__ void conv_A(const float* __restrict__ xi, const float* __restrict__ w) {
    size_t idx = (size_t)blockIdx.x * blockDim.x + threadIdx.x;
    size_t b = idx / 160;
    int c0 = (int)(idx - b * 160) * 4;
    if (b >= BATCHN) return;
    float4 v;
    int dc;
    if (c0 < NXI) { v = *(const float4*)(xi + b * NXI + c0); dc = c0; }
    else          { v = *(const float4*)(w + b * NSTATES + (c0 - NXI)); dc = c0 + 128; }
    __half2* dst = (__half2*)(g_AH + b * 768 + dc);
    dst[0] = __floats2half2_rn(v.x, v.y);
    dst[1] = __floats2half2_rn(v.z, v.w);
}

// ---------------- tanh forward-substitution scan (hi-only coalesced stores) ----------------
__global__ __launch_bounds__(64) void eps_kernel() {
    __shared__ float es[128 * 65];
    __shared__ float li[128];
    int tid = threadIdx.x;
    size_t b = (size_t)blockIdx.x * 64 + tid;
    for (int i = tid; i < 128; i += 64) li[i] = g_LamInv[i];
    __syncthreads();
    for (int i = 0; i < 128; ++i) {
        float v = g_pre[b * 128 + i];
        const float* __restrict__ dr = &g_D11[i * 128];
        float v0 = 0.f, v1 = 0.f, v2 = 0.f, v3 = 0.f;
        int j = 0;
        for (; j + 3 < i; j += 4) {
            v0 = fmaf(es[(j + 0) * 65 + tid], dr[j + 0], v0);
            v1 = fmaf(es[(j + 1) * 65 + tid], dr[j + 1], v1);
            v2 = fmaf(es[(j + 2) * 65 + tid], dr[j + 2], v2);
            v3 = fmaf(es[(j + 3) * 65 + tid], dr[j + 3], v3);
        }
        for (; j < i; ++j) v0 = fmaf(es[j * 65 + tid], dr[j], v0);
        v += (v0 + v1) + (v2 + v3);
        es[i * 65 + tid] = tanhf(v * li[i]);
    }
    __syncthreads();
    const size_t b0 = (size_t)blockIdx.x * 64;
    for (int r = 0; r < 64; ++r) {
        const size_t o = (b0 + r) * 768 + 512;
        g_AH[o + tid] = __float2half(es[tid * 65 + r]);
        g_AH[o + 64 + tid] = __float2half(es[(64 + tid) * 65 + r]);
    }
}

// ---------------- launch ----------------
extern "C" void kernel_launch(void* const* d_in, const int* in_sizes, int n_in,
                              void* d_out, int out_size) {
    (void)in_sizes; (void)n_in; (void)out_size;
    const float* w   = (const float*)d_in[1];
    const float* xi  = (const float*)d_in[2];
    const float* X   = (const float*)d_in[3];
    const float* Y   = (const float*)d_in[4];
    const float* B2  = (const float*)d_in[5];
    const float* C2  = (const float*)d_in[6];
    const float* D21 = (const float*)d_in[7];
    const float* D22 = (const float*)d_in[8];
    const float* D12 = (const float*)d_in[9];
    float* out   = (float*)d_out;
    float* out_u = out;
    float* out_x = out + (size_t)BATCHN * NIN;

    static cudaStream_t s2;
    static cudaEvent_t evStart, evH, evJoin;
    static bool inited = false;
    if (!inited) {
        cudaStreamCreateWithFlags(&s2, cudaStreamNonBlocking);
        cudaEventCreateWithFlags(&evStart, cudaEventDisableTiming);
        cudaEventCreateWithFlags(&evH, cudaEventDisableTiming);
        cudaEventCreateWithFlags(&evJoin, cudaEventDisableTiming);
        cudaFuncSetAttribute(mma_gemm, cudaFuncAttributeMaxDynamicSharedMemorySize, 3 * SBUFS);
        inited = true;
    }

    float* pPre;
    __half *pAH, *pWpreH, *pWoutH, *pXtH, *pXtL;
    cudaGetSymbolAddress((void**)&pPre, g_pre);
    cudaGetSymbolAddress((void**)&pAH, g_AH);
    cudaGetSymbolAddress((void**)&pWpreH, g_WpreH);
    cudaGetSymbolAddress((void**)&pWoutH, g_WoutH);
    cudaGetSymbolAddress((void**)&pXtH, g_XtH);
    cudaGetSymbolAddress((void**)&pXtL, g_XtL);

    // ---- top fork: conv_A on s2 in parallel with Xt/H on s0 ----
    cudaEventRecord(evStart, 0);
    cudaStreamWaitEvent(s2, evStart, 0);
    conv_A<<<(BATCHN * 160 + 255) / 256, 256, 0, s2>>>(xi, w);

    conv_Xt<<<dim3(HDIM / 32, HDIM / 32), dim3(32, 8)>>>(X);
    tc2H<<<228, 128>>>(pXtH, pXtL);
    cudaEventRecord(evH, 0);
    cudaStreamWaitEvent(s2, evH, 0);

    // ---- branch A (s2): Wpre/D11 from H -> pre-GEMM (fp16) -> eps ----
    build_WD<<<(LDIM * 640 + LDIM * LDIM + 255) / 256, 256, 0, s2>>>(D12);
    mma_gemm<<<dim3(1, BATCHN / 128), 256, 3 * SBUFS, s2>>>(
        pAH, pWpreH, 20, 512, 128, 768, 768, pPre, nullptr, 0);
    eps_kernel<<<BATCHN / 64, 64, 0, s2>>>();
    cudaEventRecord(evJoin, s2);

    // ---- branch B (s0): merged builders -> fused Newton (k-split) + solve tail ----
    build_all<<<(704512 + 255) / 256, 256>>>(Y, B2, C2, D21, D22);
    newton_fused<<<NWT_BLOCKS, 256>>>();

    // ---- join ----
    cudaStreamWaitEvent(0, evJoin, 0);

    // [u | xi_] = [xi|eps|w] @ Wout^T  (fp16)
    mma_gemm<<<dim3(5, BATCHN / 128), 256, 3 * SBUFS>>>(
        pAH, pWoutH, 24, 1 << 30, 0, 768, 768, out_u, out_x, 1);
}